// round 2
// baseline (speedup 1.0000x reference)
#include <cuda_runtime.h>
#include <cuda_bf16.h>
#include <math.h>

// Problem constants (fixed-shape benchmark)
#define NN 50000
#define EE 800000
#define HH 3
#define DIN 256
#define DHID 64
#define DOUT 10

// ---------------- scratch (device globals; no allocation allowed) -----------
__device__ float g_z1[NN * HH * DHID];     // [N,H,64]  38.4 MB
__device__ float g_out1[NN * HH * DHID];   // accumulator 38.4 MB
__device__ float g_es1[NN * HH];
__device__ float g_ed1[NN * HH];
__device__ float g_m1[NN * HH];
__device__ float g_den1[NN * HH];
__device__ float g_exs1[EE * HH];          // 9.6 MB
__device__ float g_h[NN * DHID];           // 12.8 MB
__device__ float g_z2[NN * HH * DOUT];     // 6 MB
__device__ float g_out2[NN * HH * DOUT];   // 6 MB
__device__ float g_es2[NN * HH];
__device__ float g_ed2[NN * HH];
__device__ float g_m2[NN * HH];
__device__ float g_den2[NN * HH];
__device__ float g_exs2[EE * HH];

// ---------------- helpers ---------------------------------------------------
__device__ __forceinline__ void atomicMaxF(float* addr, float v) {
    if (v >= 0.f) atomicMax((int*)addr, __float_as_int(v));
    else          atomicMin((unsigned int*)addr, __float_as_uint(v));
}

__device__ __forceinline__ void redAdd4(float* addr, float4 v) {
    asm volatile("red.global.add.v4.f32 [%0], {%1,%2,%3,%4};"
                 :: "l"(addr), "f"(v.x), "f"(v.y), "f"(v.z), "f"(v.w) : "memory");
}

// ---------------- init ------------------------------------------------------
__global__ void init_kernel() {
    int i = blockIdx.x * blockDim.x + threadIdx.x;
    const float NEGINF = __int_as_float(0xff800000);
    if (i < NN * HH * DHID) g_out1[i] = 0.f;
    if (i < NN * HH * DOUT) g_out2[i] = 0.f;
    if (i < NN * HH) {
        g_den1[i] = 0.f; g_den2[i] = 0.f;
        g_m1[i] = NEGINF; g_m2[i] = NEGINF;
    }
}

// ---------------- GEMM1: z1[n, h*64+e] = sum_d x[n,d] * W1[h,d,e] -----------
// BM=64, BN=64(=DHID), BK=16, 256 threads, 4x4 microtiles, grid.z = head
__global__ void gemm1_kernel(const float* __restrict__ x,
                             const float* __restrict__ W1) {
    __shared__ float As[16][68];   // transposed A tile [k][m], padded
    __shared__ float Bs[16][68];   // [k][n], padded
    const int h  = blockIdx.z;
    const int m0 = blockIdx.x * 64;
    const float* W = W1 + h * DIN * DHID;
    const int tid = threadIdx.x;
    const int tx = tid & 15, ty = tid >> 4;

    float acc[4][4];
    #pragma unroll
    for (int i = 0; i < 4; i++)
        #pragma unroll
        for (int j = 0; j < 4; j++) acc[i][j] = 0.f;

    for (int kk = 0; kk < DIN; kk += 16) {
        {   // A tile: rows m0..m0+63, k kk..kk+15 (one float4 per thread)
            int row = tid >> 2, q = tid & 3;
            int gr = m0 + row;
            float4 v = make_float4(0.f, 0.f, 0.f, 0.f);
            if (gr < NN) v = *(const float4*)(x + (size_t)gr * DIN + kk + q * 4);
            As[q * 4 + 0][row] = v.x;
            As[q * 4 + 1][row] = v.y;
            As[q * 4 + 2][row] = v.z;
            As[q * 4 + 3][row] = v.w;
        }
        {   // B tile: k rows kk..kk+15, 64 cols
            int row = tid >> 4, q = tid & 15;
            float4 v = *(const float4*)(W + (size_t)(kk + row) * DHID + q * 4);
            *(float4*)&Bs[row][q * 4] = v;
        }
        __syncthreads();
        #pragma unroll
        for (int k = 0; k < 16; k++) {
            float4 a4 = *(float4*)&As[k][ty * 4];
            float4 b4 = *(float4*)&Bs[k][tx * 4];
            float a[4] = {a4.x, a4.y, a4.z, a4.w};
            float b[4] = {b4.x, b4.y, b4.z, b4.w};
            #pragma unroll
            for (int i = 0; i < 4; i++)
                #pragma unroll
                for (int j = 0; j < 4; j++) acc[i][j] += a[i] * b[j];
        }
        __syncthreads();
    }
    #pragma unroll
    for (int i = 0; i < 4; i++) {
        int gr = m0 + ty * 4 + i;
        if (gr < NN) {
            #pragma unroll
            for (int j = 0; j < 4; j++)
                g_z1[(size_t)gr * (HH * DHID) + h * DHID + tx * 4 + j] = acc[i][j];
        }
    }
}

// ---------------- attention coefficients layer 1 (warp per (n,h)) ----------
__global__ void attn1_kernel(const float* __restrict__ as1,
                             const float* __restrict__ ad1) {
    int gw = (blockIdx.x * blockDim.x + threadIdx.x) >> 5;
    int lane = threadIdx.x & 31;
    if (gw >= NN * HH) return;
    int n = gw / HH, h = gw % HH;
    const float* z = g_z1 + (size_t)n * (HH * DHID) + h * DHID;
    const float* ws = as1 + h * DHID;
    const float* wd = ad1 + h * DHID;
    float vs = z[lane] * ws[lane] + z[lane + 32] * ws[lane + 32];
    float vd = z[lane] * wd[lane] + z[lane + 32] * wd[lane + 32];
    #pragma unroll
    for (int o = 16; o; o >>= 1) {
        vs += __shfl_xor_sync(0xffffffffu, vs, o);
        vd += __shfl_xor_sync(0xffffffffu, vd, o);
    }
    if (lane == 0) { g_es1[gw] = vs; g_ed1[gw] = vd; }
}

// ---------------- edge passes layer 1 ---------------------------------------
__global__ void passA1(const int* __restrict__ ei) {
    int idx = blockIdx.x * blockDim.x + threadIdx.x;
    if (idx >= EE * HH) return;
    int e = idx / HH, h = idx - e * HH;
    int src = ei[e], dst = ei[EE + e];
    float v = g_es1[src * HH + h] + g_ed1[dst * HH + h];
    v = (v > 0.f) ? v : 0.2f * v;
    atomicMaxF(&g_m1[dst * HH + h], v);
}

__global__ void passB1(const int* __restrict__ ei) {
    int idx = blockIdx.x * blockDim.x + threadIdx.x;
    if (idx >= EE * HH) return;
    int e = idx / HH, h = idx - e * HH;
    int src = ei[e], dst = ei[EE + e];
    float v = g_es1[src * HH + h] + g_ed1[dst * HH + h];
    v = (v > 0.f) ? v : 0.2f * v;
    float ex = expf(v - g_m1[dst * HH + h]);
    g_exs1[idx] = ex;
    atomicAdd(&g_den1[dst * HH + h], ex);
}

// 48 threads per edge: each covers one float4 of the 192-float z1 row
__global__ void passC1(const int* __restrict__ ei) {
    int idx = blockIdx.x * blockDim.x + threadIdx.x;
    if (idx >= EE * 48) return;
    int e = idx / 48, c = idx - e * 48;
    int h = c >> 4;
    int src = ei[e], dst = ei[EE + e];
    float alpha = g_exs1[e * HH + h] / (g_den1[dst * HH + h] + 1e-16f);
    float4 v = *(const float4*)&g_z1[(size_t)src * 192 + c * 4];
    v.x *= alpha; v.y *= alpha; v.z *= alpha; v.w *= alpha;
    redAdd4(&g_out1[(size_t)dst * 192 + c * 4], v);
}

// ---------------- mean over heads + ELU -------------------------------------
__global__ void meanelu_kernel() {
    int idx = blockIdx.x * blockDim.x + threadIdx.x;
    if (idx >= NN * DHID) return;
    int n = idx >> 6, d = idx & 63;
    const float* o = g_out1 + (size_t)n * 192;
    float s = (o[d] + o[64 + d] + o[128 + d]) * (1.f / 3.f);
    g_h[idx] = (s > 0.f) ? s : expm1f(s);
}

// ---------------- GEMM2: z2[n, h*10+o] = sum_k h[n,k] * W2[h,k,o] -----------
__global__ void gemm2_kernel(const float* __restrict__ W2) {
    __shared__ float hs[64][65];
    __shared__ float Ws[HH * DHID * DOUT];   // 1920
    int n0 = blockIdx.x * 64;
    int tid = threadIdx.x;
    for (int i = tid; i < HH * DHID * DOUT; i += 256) Ws[i] = W2[i];
    for (int i = tid; i < 64 * 64; i += 256) {
        int nl = i >> 6, d = i & 63;
        int gn = n0 + nl;
        hs[nl][d] = (gn < NN) ? g_h[(size_t)gn * DHID + d] : 0.f;
    }
    __syncthreads();
    for (int i = tid; i < 64 * HH * DOUT; i += 256) {
        int nl = i / 30, c = i - nl * 30;
        int gn = n0 + nl;
        if (gn >= NN) continue;
        int h = c / DOUT, o = c - h * DOUT;
        const float* w = Ws + h * (DHID * DOUT) + o;
        float s = 0.f;
        #pragma unroll
        for (int k = 0; k < DHID; k++) s += hs[nl][k] * w[k * DOUT];
        g_z2[(size_t)gn * (HH * DOUT) + c] = s;
    }
}

__global__ void attn2_kernel(const float* __restrict__ as2,
                             const float* __restrict__ ad2) {
    int idx = blockIdx.x * blockDim.x + threadIdx.x;
    if (idx >= NN * HH) return;
    int n = idx / HH, h = idx - n * HH;
    const float* z = g_z2 + (size_t)n * (HH * DOUT) + h * DOUT;
    float vs = 0.f, vd = 0.f;
    #pragma unroll
    for (int o = 0; o < DOUT; o++) {
        vs += z[o] * as2[h * DOUT + o];
        vd += z[o] * ad2[h * DOUT + o];
    }
    g_es2[idx] = vs; g_ed2[idx] = vd;
}

__global__ void passA2(const int* __restrict__ ei) {
    int idx = blockIdx.x * blockDim.x + threadIdx.x;
    if (idx >= EE * HH) return;
    int e = idx / HH, h = idx - e * HH;
    int src = ei[e], dst = ei[EE + e];
    float v = g_es2[src * HH + h] + g_ed2[dst * HH + h];
    v = (v > 0.f) ? v : 0.2f * v;
    atomicMaxF(&g_m2[dst * HH + h], v);
}

__global__ void passB2(const int* __restrict__ ei) {
    int idx = blockIdx.x * blockDim.x + threadIdx.x;
    if (idx >= EE * HH) return;
    int e = idx / HH, h = idx - e * HH;
    int src = ei[e], dst = ei[EE + e];
    float v = g_es2[src * HH + h] + g_ed2[dst * HH + h];
    v = (v > 0.f) ? v : 0.2f * v;
    float ex = expf(v - g_m2[dst * HH + h]);
    g_exs2[idx] = ex;
    atomicAdd(&g_den2[dst * HH + h], ex);
}

// 30 threads per edge (one scalar each)
__global__ void passC2(const int* __restrict__ ei) {
    int idx = blockIdx.x * blockDim.x + threadIdx.x;
    if (idx >= EE * 30) return;
    int e = idx / 30, c = idx - e * 30;
    int h = c / DOUT;
    int src = ei[e], dst = ei[EE + e];
    float alpha = g_exs2[e * HH + h] / (g_den2[dst * HH + h] + 1e-16f);
    float v = g_z2[(size_t)src * 30 + c] * alpha;
    atomicAdd(&g_out2[(size_t)dst * 30 + c], v);
}

// ---------------- final: mean heads, write h and log_softmax ----------------
__global__ void final_kernel(float* __restrict__ out, int half) {
    int n = blockIdx.x * blockDim.x + threadIdx.x;
    if (n >= NN) return;
    const float* o = g_out2 + (size_t)n * 30;
    float t[DOUT];
    float m = -INFINITY;
    #pragma unroll
    for (int i = 0; i < DOUT; i++) {
        t[i] = (o[i] + o[10 + i] + o[20 + i]) * (1.f / 3.f);
        m = fmaxf(m, t[i]);
    }
    float s = 0.f;
    #pragma unroll
    for (int i = 0; i < DOUT; i++) s += expf(t[i] - m);
    float lse = logf(s) + m;
    #pragma unroll
    for (int i = 0; i < DOUT; i++) {
        out[(size_t)n * DOUT + i] = t[i];
        out[half + (size_t)n * DOUT + i] = t[i] - lse;
    }
}

// ---------------- launcher --------------------------------------------------
extern "C" void kernel_launch(void* const* d_in, const int* in_sizes, int n_in,
                              void* d_out, int out_size) {
    const float* x   = (const float*)d_in[0];
    const int*   ei  = (const int*)d_in[1];
    const float* W1  = (const float*)d_in[2];
    const float* as1 = (const float*)d_in[3];
    const float* ad1 = (const float*)d_in[4];
    const float* W2  = (const float*)d_in[5];
    const float* as2 = (const float*)d_in[6];
    const float* ad2 = (const float*)d_in[7];
    float* out = (float*)d_out;
    int half = out_size / 2;   // h part then log_softmax part

    init_kernel<<<(NN * HH * DHID + 255) / 256, 256>>>();

    dim3 g1((NN + 63) / 64, 1, HH);
    gemm1_kernel<<<g1, 256>>>(x, W1);

    attn1_kernel<<<(NN * HH * 32 + 255) / 256, 256>>>(as1, ad1);

    passA1<<<(EE * HH + 255) / 256, 256>>>(ei);
    passB1<<<(EE * HH + 255) / 256, 256>>>(ei);
    passC1<<<(EE * 48 + 255) / 256, 256>>>(ei);

    meanelu_kernel<<<(NN * DHID + 255) / 256, 256>>>();

    gemm2_kernel<<<(NN + 63) / 64, 256>>>(W2);
    attn2_kernel<<<(NN * HH + 255) / 256, 256>>>(as2, ad2);

    passA2<<<(EE * HH + 255) / 256, 256>>>(ei);
    passB2<<<(EE * HH + 255) / 256, 256>>>(ei);
    passC2<<<(EE * 30 + 255) / 256, 256>>>(ei);

    final_kernel<<<(NN + 255) / 256, 256>>>(out, half);
}

// round 3
// speedup vs baseline: 1.2439x; 1.2439x over previous
#include <cuda_runtime.h>
#include <cuda_bf16.h>
#include <math.h>

// Problem constants (fixed-shape benchmark)
#define NN 50000
#define EE 800000
#define HH 3
#define DIN 256
#define DHID 64
#define DOUT 10

// ---------------- scratch (device globals; no allocation allowed) -----------
__device__ float g_z1[NN * HH * DHID];     // [N,192]  38.4 MB
__device__ float g_out1[NN * HH * DHID];   // unnormalized accumulator
__device__ float g_es1[NN * HH];
__device__ float g_ed1[NN * HH];
__device__ float g_den1[NN * HH];
__device__ float g_exs1[EE * HH];          // 9.6 MB
__device__ float g_h[NN * DHID];           // 12.8 MB
__device__ float g_z2[NN * HH * DOUT];     // [N,30]
__device__ float g_out2[NN * HH * DOUT];   // unnormalized accumulator
__device__ float g_es2[NN * HH];
__device__ float g_ed2[NN * HH];
__device__ float g_den2[NN * HH];
__device__ float g_exs2[EE * HH];

// ---------------- helpers ---------------------------------------------------
__device__ __forceinline__ void redAdd4(float* addr, float4 v) {
    asm volatile("red.global.add.v4.f32 [%0], {%1,%2,%3,%4};"
                 :: "l"(addr), "f"(v.x), "f"(v.y), "f"(v.z), "f"(v.w) : "memory");
}
__device__ __forceinline__ void redAdd2(float* addr, float2 v) {
    asm volatile("red.global.add.v2.f32 [%0], {%1,%2};"
                 :: "l"(addr), "f"(v.x), "f"(v.y) : "memory");
}

// ---------------- init ------------------------------------------------------
__global__ void init_kernel() {
    int i = blockIdx.x * blockDim.x + threadIdx.x;
    if (i < NN * HH * DHID) g_out1[i] = 0.f;
    if (i < NN * HH * DOUT) g_out2[i] = 0.f;
    if (i < NN * HH) { g_den1[i] = 0.f; g_den2[i] = 0.f; }
}

// ---------------- GEMM1: z1[n, h*64+e] = sum_d x[n,d] * W1[h,d,e] -----------
// BM=64, BN=192 (all 3 heads), BK=16, 256 threads, 4x12 microtiles.
// x tile is loaded ONCE and reused across all heads.
__global__ void gemm1_kernel(const float* __restrict__ x,
                             const float* __restrict__ W1) {
    __shared__ float As[16][68];    // [k][m], padded
    __shared__ float Bs[16][196];   // [k][n=192], padded
    const int m0 = blockIdx.x * 64;
    const int tid = threadIdx.x;
    const int tx = tid & 15;        // col group: 12 cols each
    const int ty = tid >> 4;        // row group: 4 rows each

    float acc[4][12];
    #pragma unroll
    for (int i = 0; i < 4; i++)
        #pragma unroll
        for (int j = 0; j < 12; j++) acc[i][j] = 0.f;

    const int arow = tid >> 2, aq = tid & 3;      // A loader mapping
    const int brow = tid >> 4, bq = tid & 15;     // B loader mapping

    for (int kk = 0; kk < DIN; kk += 16) {
        {   // A tile: rows m0..m0+63, k kk..kk+15
            int gr = m0 + arow;
            float4 v = make_float4(0.f, 0.f, 0.f, 0.f);
            if (gr < NN) v = *(const float4*)(x + (size_t)gr * DIN + kk + aq * 4);
            As[aq * 4 + 0][arow] = v.x;
            As[aq * 4 + 1][arow] = v.y;
            As[aq * 4 + 2][arow] = v.z;
            As[aq * 4 + 3][arow] = v.w;
        }
        #pragma unroll
        for (int h = 0; h < HH; h++) {   // B tile, per head 16x64
            float4 v = *(const float4*)(W1 + h * (DIN * DHID)
                                         + (size_t)(kk + brow) * DHID + bq * 4);
            *(float4*)&Bs[brow][h * 64 + bq * 4] = v;
        }
        __syncthreads();
        #pragma unroll
        for (int k = 0; k < 16; k++) {
            float4 a4 = *(float4*)&As[k][ty * 4];
            float a[4] = {a4.x, a4.y, a4.z, a4.w};
            float b[12];
            *(float4*)&b[0] = *(float4*)&Bs[k][tx * 12];
            *(float4*)&b[4] = *(float4*)&Bs[k][tx * 12 + 4];
            *(float4*)&b[8] = *(float4*)&Bs[k][tx * 12 + 8];
            #pragma unroll
            for (int i = 0; i < 4; i++)
                #pragma unroll
                for (int j = 0; j < 12; j++) acc[i][j] += a[i] * b[j];
        }
        __syncthreads();
    }
    #pragma unroll
    for (int i = 0; i < 4; i++) {
        int gr = m0 + ty * 4 + i;
        if (gr < NN) {
            float* dst = g_z1 + (size_t)gr * 192 + tx * 12;
            *(float4*)&dst[0] = *(float4*)&acc[i][0];
            *(float4*)&dst[4] = *(float4*)&acc[i][4];
            *(float4*)&dst[8] = *(float4*)&acc[i][8];
        }
    }
}

// ---------------- attention coefficients layer 1 (warp per (n,h)) ----------
__global__ void attn1_kernel(const float* __restrict__ as1,
                             const float* __restrict__ ad1) {
    int gw = (blockIdx.x * blockDim.x + threadIdx.x) >> 5;
    int lane = threadIdx.x & 31;
    if (gw >= NN * HH) return;
    int n = gw / HH, h = gw % HH;
    const float* z = g_z1 + (size_t)n * (HH * DHID) + h * DHID;
    const float* ws = as1 + h * DHID;
    const float* wd = ad1 + h * DHID;
    float vs = z[lane] * ws[lane] + z[lane + 32] * ws[lane + 32];
    float vd = z[lane] * wd[lane] + z[lane + 32] * wd[lane + 32];
    #pragma unroll
    for (int o = 16; o; o >>= 1) {
        vs += __shfl_xor_sync(0xffffffffu, vs, o);
        vd += __shfl_xor_sync(0xffffffffu, vd, o);
    }
    if (lane == 0) { g_es1[gw] = vs; g_ed1[gw] = vd; }
}

// ---------------- edge pass B layer 1: ex = exp(leaky(es+ed)); den += ex ----
__global__ void passB1(const int* __restrict__ ei) {
    int idx = blockIdx.x * blockDim.x + threadIdx.x;
    if (idx >= EE * HH) return;
    int e = idx / HH, h = idx - e * HH;
    int src = ei[e], dst = ei[EE + e];
    float v = g_es1[src * HH + h] + g_ed1[dst * HH + h];
    v = (v > 0.f) ? v : 0.2f * v;
    float ex = __expf(v);
    g_exs1[idx] = ex;
    atomicAdd(&g_den1[dst * HH + h], ex);
}

// ---------------- edge pass C layer 1: out1[dst] += ex * z1[src] ------------
// 48 threads per edge: one float4 each over the 192-float row
__global__ void passC1(const int* __restrict__ ei) {
    int idx = blockIdx.x * blockDim.x + threadIdx.x;
    if (idx >= EE * 48) return;
    int e = idx / 48, c = idx - e * 48;
    int h = c >> 4;
    int src = ei[e], dst = ei[EE + e];
    float ex = g_exs1[e * HH + h];
    float4 v = *(const float4*)&g_z1[(size_t)src * 192 + c * 4];
    v.x *= ex; v.y *= ex; v.z *= ex; v.w *= ex;
    redAdd4(&g_out1[(size_t)dst * 192 + c * 4], v);
}

// ---------------- normalize + mean over heads + ELU -------------------------
__global__ void meanelu_kernel() {
    int idx = blockIdx.x * blockDim.x + threadIdx.x;
    if (idx >= NN * DHID) return;
    int n = idx >> 6, d = idx & 63;
    const float* o = g_out1 + (size_t)n * 192;
    const float* dn = g_den1 + n * HH;
    float s = o[d]       / (dn[0] + 1e-16f)
            + o[64 + d]  / (dn[1] + 1e-16f)
            + o[128 + d] / (dn[2] + 1e-16f);
    s *= (1.f / 3.f);
    g_h[idx] = (s > 0.f) ? s : expm1f(s);
}

// ---------------- GEMM2: z2[n, h*10+o] = sum_k h[n,k] * W2[h,k,o] -----------
__global__ void gemm2_kernel(const float* __restrict__ W2) {
    __shared__ float hs[64][65];
    __shared__ float Ws[HH * DHID * DOUT];   // 1920
    int n0 = blockIdx.x * 64;
    int tid = threadIdx.x;
    for (int i = tid; i < HH * DHID * DOUT; i += 256) Ws[i] = W2[i];
    for (int i = tid; i < 64 * 64; i += 256) {
        int nl = i >> 6, d = i & 63;
        int gn = n0 + nl;
        hs[nl][d] = (gn < NN) ? g_h[(size_t)gn * DHID + d] : 0.f;
    }
    __syncthreads();
    for (int i = tid; i < 64 * HH * DOUT; i += 256) {
        int nl = i / 30, c = i - nl * 30;
        int gn = n0 + nl;
        if (gn >= NN) continue;
        int h = c / DOUT, o = c - h * DOUT;
        const float* w = Ws + h * (DHID * DOUT) + o;
        float s = 0.f;
        #pragma unroll
        for (int k = 0; k < DHID; k++) s += hs[nl][k] * w[k * DOUT];
        g_z2[(size_t)gn * (HH * DOUT) + c] = s;
    }
}

__global__ void attn2_kernel(const float* __restrict__ as2,
                             const float* __restrict__ ad2) {
    int idx = blockIdx.x * blockDim.x + threadIdx.x;
    if (idx >= NN * HH) return;
    int n = idx / HH, h = idx - n * HH;
    const float* z = g_z2 + (size_t)n * (HH * DOUT) + h * DOUT;
    float vs = 0.f, vd = 0.f;
    #pragma unroll
    for (int o = 0; o < DOUT; o++) {
        vs += z[o] * as2[h * DOUT + o];
        vd += z[o] * ad2[h * DOUT + o];
    }
    g_es2[idx] = vs; g_ed2[idx] = vd;
}

__global__ void passB2(const int* __restrict__ ei) {
    int idx = blockIdx.x * blockDim.x + threadIdx.x;
    if (idx >= EE * HH) return;
    int e = idx / HH, h = idx - e * HH;
    int src = ei[e], dst = ei[EE + e];
    float v = g_es2[src * HH + h] + g_ed2[dst * HH + h];
    v = (v > 0.f) ? v : 0.2f * v;
    float ex = __expf(v);
    g_exs2[idx] = ex;
    atomicAdd(&g_den2[dst * HH + h], ex);
}

// 15 threads per edge, float2 each (head = c/5, clean: 5 float2 per 10-float head)
__global__ void passC2(const int* __restrict__ ei) {
    int idx = blockIdx.x * blockDim.x + threadIdx.x;
    if (idx >= EE * 15) return;
    int e = idx / 15, c = idx - e * 15;
    int h = c / 5;
    int src = ei[e], dst = ei[EE + e];
    float ex = g_exs2[e * HH + h];
    float2 v = *(const float2*)&g_z2[(size_t)src * 30 + c * 2];
    v.x *= ex; v.y *= ex;
    redAdd2(&g_out2[(size_t)dst * 30 + c * 2], v);
}

// ---------------- final: normalize, mean heads, h + log_softmax -------------
__global__ void final_kernel(float* __restrict__ out, int half) {
    int n = blockIdx.x * blockDim.x + threadIdx.x;
    if (n >= NN) return;
    const float* o = g_out2 + (size_t)n * 30;
    const float* dn = g_den2 + n * HH;
    float inv0 = 1.f / (dn[0] + 1e-16f);
    float inv1 = 1.f / (dn[1] + 1e-16f);
    float inv2 = 1.f / (dn[2] + 1e-16f);
    float t[DOUT];
    float m = -INFINITY;
    #pragma unroll
    for (int i = 0; i < DOUT; i++) {
        t[i] = (o[i] * inv0 + o[10 + i] * inv1 + o[20 + i] * inv2) * (1.f / 3.f);
        m = fmaxf(m, t[i]);
    }
    float s = 0.f;
    #pragma unroll
    for (int i = 0; i < DOUT; i++) s += expf(t[i] - m);
    float lse = logf(s) + m;
    #pragma unroll
    for (int i = 0; i < DOUT; i++) {
        out[(size_t)n * DOUT + i] = t[i];
        out[half + (size_t)n * DOUT + i] = t[i] - lse;
    }
}

// ---------------- launcher --------------------------------------------------
extern "C" void kernel_launch(void* const* d_in, const int* in_sizes, int n_in,
                              void* d_out, int out_size) {
    const float* x   = (const float*)d_in[0];
    const int*   ei  = (const int*)d_in[1];
    const float* W1  = (const float*)d_in[2];
    const float* as1 = (const float*)d_in[3];
    const float* ad1 = (const float*)d_in[4];
    const float* W2  = (const float*)d_in[5];
    const float* as2 = (const float*)d_in[6];
    const float* ad2 = (const float*)d_in[7];
    float* out = (float*)d_out;
    int half = out_size / 2;

    init_kernel<<<(NN * HH * DHID + 255) / 256, 256>>>();

    gemm1_kernel<<<(NN + 63) / 64, 256>>>(x, W1);
    attn1_kernel<<<(NN * HH * 32 + 255) / 256, 256>>>(as1, ad1);

    passB1<<<(EE * HH + 255) / 256, 256>>>(ei);
    passC1<<<(EE * 48 + 255) / 256, 256>>>(ei);

    meanelu_kernel<<<(NN * DHID + 255) / 256, 256>>>();

    gemm2_kernel<<<(NN + 63) / 64, 256>>>(W2);
    attn2_kernel<<<(NN * HH + 255) / 256, 256>>>(as2, ad2);

    passB2<<<(EE * HH + 255) / 256, 256>>>(ei);
    passC2<<<(EE * 15 + 255) / 256, 256>>>(ei);

    final_kernel<<<(NN + 255) / 256, 256>>>(out, half);
}

// round 4
// speedup vs baseline: 1.2464x; 1.0020x over previous
#include <cuda_runtime.h>
#include <cuda_bf16.h>
#include <math.h>

// Problem constants (fixed-shape benchmark)
#define NN 50000
#define EE 800000
#define HH 3
#define DIN 256
#define DHID 64
#define DOUT 10

// ---------------- scratch (device globals; no allocation allowed) -----------
__device__ float g_z1[NN * HH * DHID];     // [N,192]  38.4 MB
__device__ float g_es1[NN * HH];
__device__ float g_ed1[NN * HH];
__device__ float g_exs1[EE * HH];          // 9.6 MB
__device__ float g_h[NN * DHID];           // 12.8 MB
__device__ float g_z2[NN * HH * DOUT];     // [N,30]
__device__ float g_es2[NN * HH];
__device__ float g_ed2[NN * HH];
__device__ float g_exs2[EE * HH];
// CSR (by dst), shared across both layers
__device__ int g_deg[NN];
__device__ int g_ptr[NN + 1];
__device__ int g_cursor[NN];
__device__ int g_csr_src[EE];
__device__ int g_csr_eid[EE];

// ---------------- CSR build --------------------------------------------------
__global__ void csr_zero() {
    int i = blockIdx.x * blockDim.x + threadIdx.x;
    if (i < NN) { g_deg[i] = 0; g_cursor[i] = 0; }
}

__global__ void csr_hist(const int* __restrict__ ei) {
    int e = blockIdx.x * blockDim.x + threadIdx.x;
    if (e >= EE) return;
    atomicAdd(&g_deg[ei[EE + e]], 1);
}

// single-block exclusive scan over g_deg -> g_ptr
__global__ void csr_scan() {
    __shared__ int part[1024];
    const int PER = (NN + 1023) / 1024;   // 49
    int t = threadIdx.x;
    int base = t * PER;
    int sum = 0;
    #pragma unroll 4
    for (int i = 0; i < PER; i++) {
        int idx = base + i;
        if (idx < NN) sum += g_deg[idx];
    }
    part[t] = sum;
    __syncthreads();
    // Hillis-Steele inclusive scan
    for (int o = 1; o < 1024; o <<= 1) {
        int v = (t >= o) ? part[t - o] : 0;
        __syncthreads();
        part[t] += v;
        __syncthreads();
    }
    int off = (t == 0) ? 0 : part[t - 1];   // exclusive
    for (int i = 0; i < PER; i++) {
        int idx = base + i;
        if (idx < NN) {
            g_ptr[idx] = off;
            off += g_deg[idx];
        }
    }
    if (t == 1023) g_ptr[NN] = off;
}

__global__ void csr_scatter(const int* __restrict__ ei) {
    int e = blockIdx.x * blockDim.x + threadIdx.x;
    if (e >= EE) return;
    int src = ei[e], dst = ei[EE + e];
    int pos = g_ptr[dst] + atomicAdd(&g_cursor[dst], 1);
    g_csr_src[pos] = src;
    g_csr_eid[pos] = e;
}

// ---------------- GEMM1: z1[n, h*64+e] = sum_d x[n,d] * W1[h,d,e] -----------
// BM=64, BN=192 (all 3 heads), BK=16, 256 threads, 4x12 microtiles.
__global__ void gemm1_kernel(const float* __restrict__ x,
                             const float* __restrict__ W1) {
    __shared__ float As[16][68];    // [k][m], padded
    __shared__ float Bs[16][196];   // [k][n=192], padded
    const int m0 = blockIdx.x * 64;
    const int tid = threadIdx.x;
    const int tx = tid & 15;        // col group: 12 cols each
    const int ty = tid >> 4;        // row group: 4 rows each

    float acc[4][12];
    #pragma unroll
    for (int i = 0; i < 4; i++)
        #pragma unroll
        for (int j = 0; j < 12; j++) acc[i][j] = 0.f;

    const int arow = tid >> 2, aq = tid & 3;
    const int brow = tid >> 4, bq = tid & 15;

    for (int kk = 0; kk < DIN; kk += 16) {
        {
            int gr = m0 + arow;
            float4 v = make_float4(0.f, 0.f, 0.f, 0.f);
            if (gr < NN) v = *(const float4*)(x + (size_t)gr * DIN + kk + aq * 4);
            As[aq * 4 + 0][arow] = v.x;
            As[aq * 4 + 1][arow] = v.y;
            As[aq * 4 + 2][arow] = v.z;
            As[aq * 4 + 3][arow] = v.w;
        }
        #pragma unroll
        for (int h = 0; h < HH; h++) {
            float4 v = *(const float4*)(W1 + h * (DIN * DHID)
                                         + (size_t)(kk + brow) * DHID + bq * 4);
            *(float4*)&Bs[brow][h * 64 + bq * 4] = v;
        }
        __syncthreads();
        #pragma unroll
        for (int k = 0; k < 16; k++) {
            float4 a4 = *(float4*)&As[k][ty * 4];
            float a[4] = {a4.x, a4.y, a4.z, a4.w};
            float b[12];
            *(float4*)&b[0] = *(float4*)&Bs[k][tx * 12];
            *(float4*)&b[4] = *(float4*)&Bs[k][tx * 12 + 4];
            *(float4*)&b[8] = *(float4*)&Bs[k][tx * 12 + 8];
            #pragma unroll
            for (int i = 0; i < 4; i++)
                #pragma unroll
                for (int j = 0; j < 12; j++) acc[i][j] += a[i] * b[j];
        }
        __syncthreads();
    }
    #pragma unroll
    for (int i = 0; i < 4; i++) {
        int gr = m0 + ty * 4 + i;
        if (gr < NN) {
            float* dst = g_z1 + (size_t)gr * 192 + tx * 12;
            *(float4*)&dst[0] = *(float4*)&acc[i][0];
            *(float4*)&dst[4] = *(float4*)&acc[i][4];
            *(float4*)&dst[8] = *(float4*)&acc[i][8];
        }
    }
}

// ---------------- attention coefficients layer 1 (warp per (n,h)) ----------
__global__ void attn1_kernel(const float* __restrict__ as1,
                             const float* __restrict__ ad1) {
    int gw = (blockIdx.x * blockDim.x + threadIdx.x) >> 5;
    int lane = threadIdx.x & 31;
    if (gw >= NN * HH) return;
    int n = gw / HH, h = gw % HH;
    const float* z = g_z1 + (size_t)n * (HH * DHID) + h * DHID;
    const float* ws = as1 + h * DHID;
    const float* wd = ad1 + h * DHID;
    float vs = z[lane] * ws[lane] + z[lane + 32] * ws[lane + 32];
    float vd = z[lane] * wd[lane] + z[lane + 32] * wd[lane + 32];
    #pragma unroll
    for (int o = 16; o; o >>= 1) {
        vs += __shfl_xor_sync(0xffffffffu, vs, o);
        vd += __shfl_xor_sync(0xffffffffu, vd, o);
    }
    if (lane == 0) { g_es1[gw] = vs; g_ed1[gw] = vd; }
}

// ---------------- edge pass: ex = exp(leaky(es+ed)) (no atomics) ------------
__global__ void passB1(const int* __restrict__ ei) {
    int idx = blockIdx.x * blockDim.x + threadIdx.x;
    if (idx >= EE * HH) return;
    int e = idx / HH, h = idx - e * HH;
    int src = ei[e], dst = ei[EE + e];
    float v = g_es1[src * HH + h] + g_ed1[dst * HH + h];
    v = (v > 0.f) ? v : 0.2f * v;
    g_exs1[idx] = __expf(v);
}

// ---------------- layer-1 gather aggregation + normalize + mean + ELU -------
// one block (192 threads) per dst node
__global__ void agg1_kernel() {
    int n = blockIdx.x;
    int c = threadIdx.x;            // 0..191
    int h = c >> 6;
    int beg = g_ptr[n], end = g_ptr[n + 1];
    float acc = 0.f, den = 0.f;
    for (int p = beg; p < end; p++) {
        int src = g_csr_src[p];
        int eid = g_csr_eid[p];
        float ex = g_exs1[eid * HH + h];
        den += ex;
        acc += ex * g_z1[(size_t)src * 192 + c];
    }
    __shared__ float s[192];
    s[c] = acc / (den + 1e-16f);
    __syncthreads();
    if (c < 64) {
        float v = (s[c] + s[c + 64] + s[c + 128]) * (1.f / 3.f);
        g_h[n * DHID + c] = (v > 0.f) ? v : expm1f(v);
    }
}

// ---------------- GEMM2: z2[n, h*10+o] = sum_k h[n,k] * W2[h,k,o] -----------
__global__ void gemm2_kernel(const float* __restrict__ W2) {
    __shared__ float hs[64][65];
    __shared__ float Ws[HH * DHID * DOUT];   // 1920
    int n0 = blockIdx.x * 64;
    int tid = threadIdx.x;
    for (int i = tid; i < HH * DHID * DOUT; i += 256) Ws[i] = W2[i];
    for (int i = tid; i < 64 * 64; i += 256) {
        int nl = i >> 6, d = i & 63;
        int gn = n0 + nl;
        hs[nl][d] = (gn < NN) ? g_h[(size_t)gn * DHID + d] : 0.f;
    }
    __syncthreads();
    for (int i = tid; i < 64 * HH * DOUT; i += 256) {
        int nl = i / 30, c = i - nl * 30;
        int gn = n0 + nl;
        if (gn >= NN) continue;
        int h = c / DOUT, o = c - h * DOUT;
        const float* w = Ws + h * (DHID * DOUT) + o;
        float s = 0.f;
        #pragma unroll
        for (int k = 0; k < DHID; k++) s += hs[nl][k] * w[k * DOUT];
        g_z2[(size_t)gn * (HH * DOUT) + c] = s;
    }
}

__global__ void attn2_kernel(const float* __restrict__ as2,
                             const float* __restrict__ ad2) {
    int idx = blockIdx.x * blockDim.x + threadIdx.x;
    if (idx >= NN * HH) return;
    int n = idx / HH, h = idx - n * HH;
    const float* z = g_z2 + (size_t)n * (HH * DOUT) + h * DOUT;
    float vs = 0.f, vd = 0.f;
    #pragma unroll
    for (int o = 0; o < DOUT; o++) {
        vs += z[o] * as2[h * DOUT + o];
        vd += z[o] * ad2[h * DOUT + o];
    }
    g_es2[idx] = vs; g_ed2[idx] = vd;
}

__global__ void passB2(const int* __restrict__ ei) {
    int idx = blockIdx.x * blockDim.x + threadIdx.x;
    if (idx >= EE * HH) return;
    int e = idx / HH, h = idx - e * HH;
    int src = ei[e], dst = ei[EE + e];
    float v = g_es2[src * HH + h] + g_ed2[dst * HH + h];
    v = (v > 0.f) ? v : 0.2f * v;
    g_exs2[idx] = __expf(v);
}

// ---------------- layer-2 gather aggregation + mean + log_softmax -----------
// one warp per dst node, 8 warps per block
__global__ void agg2_kernel(float* __restrict__ out, int half) {
    int warp = (blockIdx.x * blockDim.x + threadIdx.x) >> 5;
    int lane = threadIdx.x & 31;
    if (warp >= NN) return;
    int n = warp;
    int c = lane;                   // 0..29 active
    int h = (c < 30) ? (c / DOUT) : 0;
    int beg = g_ptr[n], end = g_ptr[n + 1];
    float acc = 0.f, den = 0.f;
    for (int p = beg; p < end; p++) {
        int src = g_csr_src[p];
        int eid = g_csr_eid[p];
        float ex = g_exs2[eid * HH + h];
        den += ex;
        if (c < 30) acc += ex * g_z2[(size_t)src * 30 + c];
    }
    float s = acc / (den + 1e-16f);
    // combine heads: t[i] = (s_i + s_{i+10} + s_{i+20}) / 3, valid for lane<10
    float s10 = __shfl_down_sync(0xffffffffu, s, 10);
    float s20 = __shfl_down_sync(0xffffffffu, s, 20);
    float t = (s + s10 + s20) * (1.f / 3.f);
    // log_softmax over lanes 0..9 (pad 10..15 for the width-16 butterfly)
    float tm = (lane < 10) ? t : -INFINITY;
    #pragma unroll
    for (int o = 8; o; o >>= 1)
        tm = fmaxf(tm, __shfl_xor_sync(0xffffffffu, tm, o, 16));
    float te = (lane < 10) ? __expf(t - tm) : 0.f;
    #pragma unroll
    for (int o = 8; o; o >>= 1)
        te += __shfl_xor_sync(0xffffffffu, te, o, 16);
    float lse = __logf(te) + tm;
    if (lane < 10) {
        out[(size_t)n * DOUT + lane] = t;
        out[half + (size_t)n * DOUT + lane] = t - lse;
    }
}

// ---------------- launcher --------------------------------------------------
extern "C" void kernel_launch(void* const* d_in, const int* in_sizes, int n_in,
                              void* d_out, int out_size) {
    const float* x   = (const float*)d_in[0];
    const int*   ei  = (const int*)d_in[1];
    const float* W1  = (const float*)d_in[2];
    const float* as1 = (const float*)d_in[3];
    const float* ad1 = (const float*)d_in[4];
    const float* W2  = (const float*)d_in[5];
    const float* as2 = (const float*)d_in[6];
    const float* ad2 = (const float*)d_in[7];
    float* out = (float*)d_out;
    int half = out_size / 2;

    // CSR build (graph shared by both layers)
    csr_zero<<<(NN + 255) / 256, 256>>>();
    csr_hist<<<(EE + 255) / 256, 256>>>(ei);
    csr_scan<<<1, 1024>>>();
    csr_scatter<<<(EE + 255) / 256, 256>>>(ei);

    // layer 1
    gemm1_kernel<<<(NN + 63) / 64, 256>>>(x, W1);
    attn1_kernel<<<(NN * HH * 32 + 255) / 256, 256>>>(as1, ad1);
    passB1<<<(EE * HH + 255) / 256, 256>>>(ei);
    agg1_kernel<<<NN, 192>>>();

    // layer 2
    gemm2_kernel<<<(NN + 63) / 64, 256>>>(W2);
    attn2_kernel<<<(NN * HH + 255) / 256, 256>>>(as2, ad2);
    passB2<<<(EE * HH + 255) / 256, 256>>>(ei);
    agg2_kernel<<<(NN * 32 + 255) / 256, 256>>>(out, half);
}

// round 5
// speedup vs baseline: 1.2567x; 1.0083x over previous
#include <cuda_runtime.h>
#include <cuda_bf16.h>
#include <math.h>

// Problem constants (fixed-shape benchmark)
#define NN 50000
#define EE 800000
#define HH 3
#define DIN 256
#define DHID 64
#define DOUT 10

// ---------------- scratch (device globals; no allocation allowed) -----------
__device__ float g_z1[NN * HH * DHID];     // [N,192]  38.4 MB
__device__ float g_es1[NN * HH];
__device__ float g_ed1[NN * HH];
__device__ float g_h[NN * DHID];           // 12.8 MB
__device__ float g_z2[NN * HH * DOUT];     // [N,30]
__device__ float g_es2[NN * HH];
__device__ float g_ed2[NN * HH];
// CSR (by dst), shared across both layers
__device__ int g_deg[NN];
__device__ int g_ptr[NN + 1];
__device__ int g_cursor[NN];
__device__ int g_csr_src[EE];

// ---------------- CSR build --------------------------------------------------
__global__ void csr_zero() {
    int i = blockIdx.x * blockDim.x + threadIdx.x;
    if (i < NN) { g_deg[i] = 0; g_cursor[i] = 0; }
}

__global__ void csr_hist(const int* __restrict__ ei) {
    int e = blockIdx.x * blockDim.x + threadIdx.x;
    if (e >= EE) return;
    atomicAdd(&g_deg[ei[EE + e]], 1);
}

// single-block exclusive scan over g_deg -> g_ptr
__global__ void csr_scan() {
    __shared__ int part[1024];
    const int PER = (NN + 1023) / 1024;   // 49
    int t = threadIdx.x;
    int base = t * PER;
    int sum = 0;
    #pragma unroll 4
    for (int i = 0; i < PER; i++) {
        int idx = base + i;
        if (idx < NN) sum += g_deg[idx];
    }
    part[t] = sum;
    __syncthreads();
    for (int o = 1; o < 1024; o <<= 1) {
        int v = (t >= o) ? part[t - o] : 0;
        __syncthreads();
        part[t] += v;
        __syncthreads();
    }
    int off = (t == 0) ? 0 : part[t - 1];   // exclusive
    for (int i = 0; i < PER; i++) {
        int idx = base + i;
        if (idx < NN) {
            g_ptr[idx] = off;
            off += g_deg[idx];
        }
    }
    if (t == 1023) g_ptr[NN] = off;
}

__global__ void csr_scatter(const int* __restrict__ ei) {
    int e = blockIdx.x * blockDim.x + threadIdx.x;
    if (e >= EE) return;
    int src = ei[e], dst = ei[EE + e];
    int pos = g_ptr[dst] + atomicAdd(&g_cursor[dst], 1);
    g_csr_src[pos] = src;
}

// ---------------- GEMM1: z1[n, h*64+e] = sum_d x[n,d] * W1[h,d,e] -----------
// BM=64, BN=192 (all 3 heads), BK=16, 256 threads, 4x12 microtiles.
__global__ void gemm1_kernel(const float* __restrict__ x,
                             const float* __restrict__ W1) {
    __shared__ float As[16][68];    // [k][m], padded
    __shared__ float Bs[16][196];   // [k][n=192], padded
    const int m0 = blockIdx.x * 64;
    const int tid = threadIdx.x;
    const int tx = tid & 15;        // col group: 12 cols each
    const int ty = tid >> 4;        // row group: 4 rows each

    float acc[4][12];
    #pragma unroll
    for (int i = 0; i < 4; i++)
        #pragma unroll
        for (int j = 0; j < 12; j++) acc[i][j] = 0.f;

    const int arow = tid >> 2, aq = tid & 3;
    const int brow = tid >> 4, bq = tid & 15;

    for (int kk = 0; kk < DIN; kk += 16) {
        {
            int gr = m0 + arow;
            float4 v = make_float4(0.f, 0.f, 0.f, 0.f);
            if (gr < NN) v = *(const float4*)(x + (size_t)gr * DIN + kk + aq * 4);
            As[aq * 4 + 0][arow] = v.x;
            As[aq * 4 + 1][arow] = v.y;
            As[aq * 4 + 2][arow] = v.z;
            As[aq * 4 + 3][arow] = v.w;
        }
        #pragma unroll
        for (int h = 0; h < HH; h++) {
            float4 v = *(const float4*)(W1 + h * (DIN * DHID)
                                         + (size_t)(kk + brow) * DHID + bq * 4);
            *(float4*)&Bs[brow][h * 64 + bq * 4] = v;
        }
        __syncthreads();
        #pragma unroll
        for (int k = 0; k < 16; k++) {
            float4 a4 = *(float4*)&As[k][ty * 4];
            float a[4] = {a4.x, a4.y, a4.z, a4.w};
            float b[12];
            *(float4*)&b[0] = *(float4*)&Bs[k][tx * 12];
            *(float4*)&b[4] = *(float4*)&Bs[k][tx * 12 + 4];
            *(float4*)&b[8] = *(float4*)&Bs[k][tx * 12 + 8];
            #pragma unroll
            for (int i = 0; i < 4; i++)
                #pragma unroll
                for (int j = 0; j < 12; j++) acc[i][j] += a[i] * b[j];
        }
        __syncthreads();
    }
    #pragma unroll
    for (int i = 0; i < 4; i++) {
        int gr = m0 + ty * 4 + i;
        if (gr < NN) {
            float* dst = g_z1 + (size_t)gr * 192 + tx * 12;
            *(float4*)&dst[0] = *(float4*)&acc[i][0];
            *(float4*)&dst[4] = *(float4*)&acc[i][4];
            *(float4*)&dst[8] = *(float4*)&acc[i][8];
        }
    }
}

// ---------------- attention coefficients layer 1 (warp per (n,h)) ----------
__global__ void attn1_kernel(const float* __restrict__ as1,
                             const float* __restrict__ ad1) {
    int gw = (blockIdx.x * blockDim.x + threadIdx.x) >> 5;
    int lane = threadIdx.x & 31;
    if (gw >= NN * HH) return;
    int n = gw / HH, h = gw % HH;
    const float* z = g_z1 + (size_t)n * (HH * DHID) + h * DHID;
    const float* ws = as1 + h * DHID;
    const float* wd = ad1 + h * DHID;
    float vs = z[lane] * ws[lane] + z[lane + 32] * ws[lane + 32];
    float vd = z[lane] * wd[lane] + z[lane + 32] * wd[lane + 32];
    #pragma unroll
    for (int o = 16; o; o >>= 1) {
        vs += __shfl_xor_sync(0xffffffffu, vs, o);
        vd += __shfl_xor_sync(0xffffffffu, vd, o);
    }
    if (lane == 0) { g_es1[gw] = vs; g_ed1[gw] = vd; }
}

// ---------------- layer-1 fused: softmax-weight + gather-agg + mean + ELU ---
// one block (192 threads) per dst node; ex computed in-loop (no passB kernel)
__global__ void agg1_kernel() {
    int n = blockIdx.x;
    int c = threadIdx.x;            // 0..191
    int h = c >> 6;
    __shared__ int s_src[64];
    __shared__ float s_red[192];
    int beg = g_ptr[n], end = g_ptr[n + 1];
    float ed = g_ed1[n * HH + h];
    float acc0 = 0.f, acc1 = 0.f, den = 0.f;
    for (int base = beg; base < end; base += 64) {
        int cnt = min(64, end - base);
        __syncthreads();
        if (c < cnt) s_src[c] = g_csr_src[base + c];
        __syncthreads();
        int p2 = cnt & ~1;
        for (int j = 0; j < p2; j += 2) {
            int s0 = s_src[j], s1 = s_src[j + 1];
            float e0 = g_es1[s0 * HH + h] + ed;
            float e1 = g_es1[s1 * HH + h] + ed;
            e0 = (e0 > 0.f) ? e0 : 0.2f * e0;
            e1 = (e1 > 0.f) ? e1 : 0.2f * e1;
            float ex0 = __expf(e0), ex1 = __expf(e1);
            float z0 = g_z1[(size_t)s0 * 192 + c];
            float z1v = g_z1[(size_t)s1 * 192 + c];
            den += ex0 + ex1;
            acc0 += ex0 * z0;
            acc1 += ex1 * z1v;
        }
        if (p2 < cnt) {
            int s0 = s_src[p2];
            float e0 = g_es1[s0 * HH + h] + ed;
            e0 = (e0 > 0.f) ? e0 : 0.2f * e0;
            float ex0 = __expf(e0);
            den += ex0;
            acc0 += ex0 * g_z1[(size_t)s0 * 192 + c];
        }
    }
    s_red[c] = (acc0 + acc1) / (den + 1e-16f);
    __syncthreads();
    if (c < 64) {
        float v = (s_red[c] + s_red[c + 64] + s_red[c + 128]) * (1.f / 3.f);
        g_h[n * DHID + c] = (v > 0.f) ? v : expm1f(v);
    }
}

// ---------------- GEMM2: z2[n, h*10+o] = sum_k h[n,k] * W2[h,k,o] -----------
__global__ void gemm2_kernel(const float* __restrict__ W2) {
    __shared__ float hs[64][65];
    __shared__ float Ws[HH * DHID * DOUT];   // 1920
    int n0 = blockIdx.x * 64;
    int tid = threadIdx.x;
    for (int i = tid; i < HH * DHID * DOUT; i += 256) Ws[i] = W2[i];
    for (int i = tid; i < 64 * 64; i += 256) {
        int nl = i >> 6, d = i & 63;
        int gn = n0 + nl;
        hs[nl][d] = (gn < NN) ? g_h[(size_t)gn * DHID + d] : 0.f;
    }
    __syncthreads();
    for (int i = tid; i < 64 * HH * DOUT; i += 256) {
        int nl = i / 30, c = i - nl * 30;
        int gn = n0 + nl;
        if (gn >= NN) continue;
        int h = c / DOUT, o = c - h * DOUT;
        const float* w = Ws + h * (DHID * DOUT) + o;
        float s = 0.f;
        #pragma unroll
        for (int k = 0; k < DHID; k++) s += hs[nl][k] * w[k * DOUT];
        g_z2[(size_t)gn * (HH * DOUT) + c] = s;
    }
}

__global__ void attn2_kernel(const float* __restrict__ as2,
                             const float* __restrict__ ad2) {
    int idx = blockIdx.x * blockDim.x + threadIdx.x;
    if (idx >= NN * HH) return;
    int n = idx / HH, h = idx - n * HH;
    const float* z = g_z2 + (size_t)n * (HH * DOUT) + h * DOUT;
    float vs = 0.f, vd = 0.f;
    #pragma unroll
    for (int o = 0; o < DOUT; o++) {
        vs += z[o] * as2[h * DOUT + o];
        vd += z[o] * ad2[h * DOUT + o];
    }
    g_es2[idx] = vs; g_ed2[idx] = vd;
}

// ---------------- layer-2 fused: gather-agg + mean + log_softmax ------------
// one warp per dst node
__global__ void agg2_kernel(float* __restrict__ out, int half) {
    int warp = (blockIdx.x * blockDim.x + threadIdx.x) >> 5;
    int lane = threadIdx.x & 31;
    if (warp >= NN) return;
    int n = warp;
    int c = lane;                   // 0..29 active
    int h = (c < 30) ? (c / DOUT) : 0;
    float ed = g_ed2[n * HH + h];
    int beg = g_ptr[n], end = g_ptr[n + 1];
    float acc0 = 0.f, acc1 = 0.f, den = 0.f;
    int p = beg;
    for (; p + 1 < end; p += 2) {
        int s0 = g_csr_src[p], s1 = g_csr_src[p + 1];
        float e0 = g_es2[s0 * HH + h] + ed;
        float e1 = g_es2[s1 * HH + h] + ed;
        e0 = (e0 > 0.f) ? e0 : 0.2f * e0;
        e1 = (e1 > 0.f) ? e1 : 0.2f * e1;
        float ex0 = __expf(e0), ex1 = __expf(e1);
        den += ex0 + ex1;
        if (c < 30) {
            acc0 += ex0 * g_z2[(size_t)s0 * 30 + c];
            acc1 += ex1 * g_z2[(size_t)s1 * 30 + c];
        }
    }
    if (p < end) {
        int s0 = g_csr_src[p];
        float e0 = g_es2[s0 * HH + h] + ed;
        e0 = (e0 > 0.f) ? e0 : 0.2f * e0;
        float ex0 = __expf(e0);
        den += ex0;
        if (c < 30) acc0 += ex0 * g_z2[(size_t)s0 * 30 + c];
    }
    float s = (acc0 + acc1) / (den + 1e-16f);
    float s10 = __shfl_down_sync(0xffffffffu, s, 10);
    float s20 = __shfl_down_sync(0xffffffffu, s, 20);
    float t = (s + s10 + s20) * (1.f / 3.f);
    float tm = (lane < 10) ? t : -INFINITY;
    #pragma unroll
    for (int o = 8; o; o >>= 1)
        tm = fmaxf(tm, __shfl_xor_sync(0xffffffffu, tm, o, 16));
    float te = (lane < 10) ? __expf(t - tm) : 0.f;
    #pragma unroll
    for (int o = 8; o; o >>= 1)
        te += __shfl_xor_sync(0xffffffffu, te, o, 16);
    float lse = __logf(te) + tm;
    if (lane < 10) {
        out[(size_t)n * DOUT + lane] = t;
        out[half + (size_t)n * DOUT + lane] = t - lse;
    }
}

// ---------------- launcher --------------------------------------------------
extern "C" void kernel_launch(void* const* d_in, const int* in_sizes, int n_in,
                              void* d_out, int out_size) {
    const float* x   = (const float*)d_in[0];
    const int*   ei  = (const int*)d_in[1];
    const float* W1  = (const float*)d_in[2];
    const float* as1 = (const float*)d_in[3];
    const float* ad1 = (const float*)d_in[4];
    const float* W2  = (const float*)d_in[5];
    const float* as2 = (const float*)d_in[6];
    const float* ad2 = (const float*)d_in[7];
    float* out = (float*)d_out;
    int half = out_size / 2;

    // CSR build (graph shared by both layers)
    csr_zero<<<(NN + 255) / 256, 256>>>();
    csr_hist<<<(EE + 255) / 256, 256>>>(ei);
    csr_scan<<<1, 1024>>>();
    csr_scatter<<<(EE + 255) / 256, 256>>>(ei);

    // layer 1
    gemm1_kernel<<<(NN + 63) / 64, 256>>>(x, W1);
    attn1_kernel<<<(NN * HH * 32 + 255) / 256, 256>>>(as1, ad1);
    agg1_kernel<<<NN, 192>>>();

    // layer 2
    gemm2_kernel<<<(NN + 63) / 64, 256>>>(W2);
    attn2_kernel<<<(NN * HH + 255) / 256, 256>>>(as2, ad2);
    agg2_kernel<<<(NN * 32 + 255) / 256, 256>>>(out, half);
}

// round 6
// speedup vs baseline: 1.4187x; 1.1289x over previous
#include <cuda_runtime.h>
#include <cuda_bf16.h>
#include <math.h>

// Problem constants (fixed-shape benchmark)
#define NN 50000
#define EE 800000
#define HH 3
#define DIN 256
#define DHID 64
#define DOUT 10

// ---------------- scratch (device globals; no allocation allowed) -----------
__device__ float g_z1[NN * HH * DHID];     // [N,192]  38.4 MB
__device__ float g_es1[NN * HH];
__device__ float g_ed1[NN * HH];
__device__ float g_h[NN * DHID];           // 12.8 MB
__device__ float g_z2[NN * HH * DOUT];     // [N,30]
__device__ float g_es2[NN * HH];
__device__ float g_ed2[NN * HH];
// CSR (by dst), shared across both layers
__device__ int g_deg[NN];
__device__ int g_ptr[NN + 1];
__device__ int g_cursor[NN];
__device__ int g_csr_src[EE];

// ---------------- helpers ---------------------------------------------------
__device__ __forceinline__ unsigned int f2tf32(float f) {
    unsigned int r;
    asm("cvt.rna.tf32.f32 %0, %1;" : "=r"(r) : "f"(f));
    return r;
}

__device__ __forceinline__ void mma_tf32(float* c, const unsigned int* a,
                                         const unsigned int* b) {
    asm volatile(
        "mma.sync.aligned.m16n8k8.row.col.f32.tf32.tf32.f32 "
        "{%0,%1,%2,%3}, {%4,%5,%6,%7}, {%8,%9}, {%0,%1,%2,%3};"
        : "+f"(c[0]), "+f"(c[1]), "+f"(c[2]), "+f"(c[3])
        : "r"(a[0]), "r"(a[1]), "r"(a[2]), "r"(a[3]), "r"(b[0]), "r"(b[1]));
}

// ---------------- CSR build --------------------------------------------------
__global__ void csr_zero() {
    int i = blockIdx.x * blockDim.x + threadIdx.x;
    if (i < NN) { g_deg[i] = 0; g_cursor[i] = 0; }
}

__global__ void csr_hist(const int* __restrict__ ei) {
    int e = blockIdx.x * blockDim.x + threadIdx.x;
    if (e >= EE) return;
    atomicAdd(&g_deg[ei[EE + e]], 1);
}

// single-block exclusive scan over g_deg -> g_ptr
__global__ void csr_scan() {
    __shared__ int part[1024];
    const int PER = (NN + 1023) / 1024;   // 49
    int t = threadIdx.x;
    int base = t * PER;
    int sum = 0;
    #pragma unroll 4
    for (int i = 0; i < PER; i++) {
        int idx = base + i;
        if (idx < NN) sum += g_deg[idx];
    }
    part[t] = sum;
    __syncthreads();
    for (int o = 1; o < 1024; o <<= 1) {
        int v = (t >= o) ? part[t - o] : 0;
        __syncthreads();
        part[t] += v;
        __syncthreads();
    }
    int off = (t == 0) ? 0 : part[t - 1];   // exclusive
    for (int i = 0; i < PER; i++) {
        int idx = base + i;
        if (idx < NN) {
            g_ptr[idx] = off;
            off += g_deg[idx];
        }
    }
    if (t == 1023) g_ptr[NN] = off;
}

__global__ void csr_scatter(const int* __restrict__ ei) {
    int e = blockIdx.x * blockDim.x + threadIdx.x;
    if (e >= EE) return;
    int src = ei[e], dst = ei[EE + e];
    int pos = g_ptr[dst] + atomicAdd(&g_cursor[dst], 1);
    g_csr_src[pos] = src;
}

// ---------------- GEMM1 (tensor cores, tf32): z1 = x @ Wcat -----------------
// BM=128, BN=192, BK=16, 256 threads = 8 warps (4M x 2N), warp tile 32x96.
__global__ void gemm1_tc(const float* __restrict__ x,
                         const float* __restrict__ W1) {
    __shared__ unsigned int As[128][20];    // [m][k], pad 16->20
    __shared__ unsigned int Bs[16][196];    // [k][n=192], pad
    const int m0 = blockIdx.x * 128;
    const int tid = threadIdx.x;
    const int wid = tid >> 5, lane = tid & 31;
    const int warp_m = wid >> 1;            // 0..3 -> 32 rows each
    const int warp_n = wid & 1;             // 0..1 -> 96 cols each
    const int lr = lane >> 2;               // 0..7
    const int lc = lane & 3;                // 0..3

    float acc[2][12][4];
    #pragma unroll
    for (int mt = 0; mt < 2; mt++)
        #pragma unroll
        for (int nt = 0; nt < 12; nt++)
            #pragma unroll
            for (int q = 0; q < 4; q++) acc[mt][nt][q] = 0.f;

    for (int kk = 0; kk < DIN; kk += 16) {
        // ---- A tile: 128 rows x 16 k (512 float4, 2 per thread) ----
        #pragma unroll
        for (int r = 0; r < 2; r++) {
            int i = tid + r * 256;          // 0..511
            int row = i >> 2, q = i & 3;
            int gr = m0 + row;
            float4 v = make_float4(0.f, 0.f, 0.f, 0.f);
            if (gr < NN) v = *(const float4*)(x + (size_t)gr * DIN + kk + q * 4);
            As[row][q * 4 + 0] = f2tf32(v.x);
            As[row][q * 4 + 1] = f2tf32(v.y);
            As[row][q * 4 + 2] = f2tf32(v.z);
            As[row][q * 4 + 3] = f2tf32(v.w);
        }
        // ---- B tile: 16 k-rows x 192 cols (768 float4, 3 per thread) ----
        #pragma unroll
        for (int r = 0; r < 3; r++) {
            int i = tid + r * 256;          // 0..767
            int k = i / 48, c = (i % 48) * 4;
            int h = c >> 6, j = c & 63;
            float4 v = *(const float4*)(W1 + h * (DIN * DHID)
                                         + (size_t)(kk + k) * DHID + j);
            Bs[k][c + 0] = f2tf32(v.x);
            Bs[k][c + 1] = f2tf32(v.y);
            Bs[k][c + 2] = f2tf32(v.z);
            Bs[k][c + 3] = f2tf32(v.w);
        }
        __syncthreads();
        // ---- compute ----
        #pragma unroll
        for (int ks = 0; ks < 2; ks++) {
            int kb = ks * 8;
            unsigned int afrag[2][4];
            #pragma unroll
            for (int mt = 0; mt < 2; mt++) {
                int m = warp_m * 32 + mt * 16 + lr;
                afrag[mt][0] = As[m][kb + lc];
                afrag[mt][1] = As[m + 8][kb + lc];
                afrag[mt][2] = As[m][kb + lc + 4];
                afrag[mt][3] = As[m + 8][kb + lc + 4];
            }
            #pragma unroll
            for (int nt = 0; nt < 12; nt++) {
                int n = warp_n * 96 + nt * 8 + lr;
                unsigned int bfrag[2];
                bfrag[0] = Bs[kb + lc][n];
                bfrag[1] = Bs[kb + lc + 4][n];
                mma_tf32(acc[0][nt], afrag[0], bfrag);
                mma_tf32(acc[1][nt], afrag[1], bfrag);
            }
        }
        __syncthreads();
    }
    // ---- epilogue ----
    #pragma unroll
    for (int mt = 0; mt < 2; mt++) {
        int row0 = m0 + warp_m * 32 + mt * 16 + lr;
        #pragma unroll
        for (int nt = 0; nt < 12; nt++) {
            int col = warp_n * 96 + nt * 8 + lc * 2;
            if (row0 < NN) {
                g_z1[(size_t)row0 * 192 + col]     = acc[mt][nt][0];
                g_z1[(size_t)row0 * 192 + col + 1] = acc[mt][nt][1];
            }
            if (row0 + 8 < NN) {
                g_z1[(size_t)(row0 + 8) * 192 + col]     = acc[mt][nt][2];
                g_z1[(size_t)(row0 + 8) * 192 + col + 1] = acc[mt][nt][3];
            }
        }
    }
}

// ---------------- attention coefficients layer 1 (warp per (n,h)) ----------
__global__ void attn1_kernel(const float* __restrict__ as1,
                             const float* __restrict__ ad1) {
    int gw = (blockIdx.x * blockDim.x + threadIdx.x) >> 5;
    int lane = threadIdx.x & 31;
    if (gw >= NN * HH) return;
    int n = gw / HH, h = gw % HH;
    const float* z = g_z1 + (size_t)n * (HH * DHID) + h * DHID;
    const float* ws = as1 + h * DHID;
    const float* wd = ad1 + h * DHID;
    float vs = z[lane] * ws[lane] + z[lane + 32] * ws[lane + 32];
    float vd = z[lane] * wd[lane] + z[lane + 32] * wd[lane + 32];
    #pragma unroll
    for (int o = 16; o; o >>= 1) {
        vs += __shfl_xor_sync(0xffffffffu, vs, o);
        vd += __shfl_xor_sync(0xffffffffu, vd, o);
    }
    if (lane == 0) { g_es1[gw] = vs; g_ed1[gw] = vd; }
}

// ---------------- layer-1 fused: softmax-weight + gather-agg + mean + ELU ---
// one block (192 threads) per dst node; ex computed in-loop
__global__ void agg1_kernel() {
    int n = blockIdx.x;
    int c = threadIdx.x;            // 0..191
    int h = c >> 6;
    __shared__ int s_src[64];
    __shared__ float s_red[192];
    int beg = g_ptr[n], end = g_ptr[n + 1];
    float ed = g_ed1[n * HH + h];
    float acc0 = 0.f, acc1 = 0.f, den = 0.f;
    for (int base = beg; base < end; base += 64) {
        int cnt = min(64, end - base);
        __syncthreads();
        if (c < cnt) s_src[c] = g_csr_src[base + c];
        __syncthreads();
        int p2 = cnt & ~1;
        for (int j = 0; j < p2; j += 2) {
            int s0 = s_src[j], s1 = s_src[j + 1];
            float e0 = g_es1[s0 * HH + h] + ed;
            float e1 = g_es1[s1 * HH + h] + ed;
            e0 = (e0 > 0.f) ? e0 : 0.2f * e0;
            e1 = (e1 > 0.f) ? e1 : 0.2f * e1;
            float ex0 = __expf(e0), ex1 = __expf(e1);
            float z0 = g_z1[(size_t)s0 * 192 + c];
            float z1v = g_z1[(size_t)s1 * 192 + c];
            den += ex0 + ex1;
            acc0 += ex0 * z0;
            acc1 += ex1 * z1v;
        }
        if (p2 < cnt) {
            int s0 = s_src[p2];
            float e0 = g_es1[s0 * HH + h] + ed;
            e0 = (e0 > 0.f) ? e0 : 0.2f * e0;
            float ex0 = __expf(e0);
            den += ex0;
            acc0 += ex0 * g_z1[(size_t)s0 * 192 + c];
        }
    }
    s_red[c] = (acc0 + acc1) / (den + 1e-16f);
    __syncthreads();
    if (c < 64) {
        float v = (s_red[c] + s_red[c + 64] + s_red[c + 128]) * (1.f / 3.f);
        g_h[n * DHID + c] = (v > 0.f) ? v : expm1f(v);
    }
}

// ---------------- GEMM2: z2[n, h*10+o] = sum_k h[n,k] * W2[h,k,o] -----------
__global__ void gemm2_kernel(const float* __restrict__ W2) {
    __shared__ float hs[64][65];
    __shared__ float Ws[HH * DHID * DOUT];   // 1920
    int n0 = blockIdx.x * 64;
    int tid = threadIdx.x;
    for (int i = tid; i < HH * DHID * DOUT; i += 256) Ws[i] = W2[i];
    for (int i = tid; i < 64 * 64; i += 256) {
        int nl = i >> 6, d = i & 63;
        int gn = n0 + nl;
        hs[nl][d] = (gn < NN) ? g_h[(size_t)gn * DHID + d] : 0.f;
    }
    __syncthreads();
    for (int i = tid; i < 64 * HH * DOUT; i += 256) {
        int nl = i / 30, c = i - nl * 30;
        int gn = n0 + nl;
        if (gn >= NN) continue;
        int h = c / DOUT, o = c - h * DOUT;
        const float* w = Ws + h * (DHID * DOUT) + o;
        float s = 0.f;
        #pragma unroll
        for (int k = 0; k < DHID; k++) s += hs[nl][k] * w[k * DOUT];
        g_z2[(size_t)gn * (HH * DOUT) + c] = s;
    }
}

__global__ void attn2_kernel(const float* __restrict__ as2,
                             const float* __restrict__ ad2) {
    int idx = blockIdx.x * blockDim.x + threadIdx.x;
    if (idx >= NN * HH) return;
    int n = idx / HH, h = idx - n * HH;
    const float* z = g_z2 + (size_t)n * (HH * DOUT) + h * DOUT;
    float vs = 0.f, vd = 0.f;
    #pragma unroll
    for (int o = 0; o < DOUT; o++) {
        vs += z[o] * as2[h * DOUT + o];
        vd += z[o] * ad2[h * DOUT + o];
    }
    g_es2[idx] = vs; g_ed2[idx] = vd;
}

// ---------------- layer-2 fused: gather-agg + mean + log_softmax ------------
// one warp per dst node
__global__ void agg2_kernel(float* __restrict__ out, int half) {
    int warp = (blockIdx.x * blockDim.x + threadIdx.x) >> 5;
    int lane = threadIdx.x & 31;
    if (warp >= NN) return;
    int n = warp;
    int c = lane;                   // 0..29 active
    int h = (c < 30) ? (c / DOUT) : 0;
    float ed = g_ed2[n * HH + h];
    int beg = g_ptr[n], end = g_ptr[n + 1];
    float acc0 = 0.f, acc1 = 0.f, den = 0.f;
    int p = beg;
    for (; p + 1 < end; p += 2) {
        int s0 = g_csr_src[p], s1 = g_csr_src[p + 1];
        float e0 = g_es2[s0 * HH + h] + ed;
        float e1 = g_es2[s1 * HH + h] + ed;
        e0 = (e0 > 0.f) ? e0 : 0.2f * e0;
        e1 = (e1 > 0.f) ? e1 : 0.2f * e1;
        float ex0 = __expf(e0), ex1 = __expf(e1);
        den += ex0 + ex1;
        if (c < 30) {
            acc0 += ex0 * g_z2[(size_t)s0 * 30 + c];
            acc1 += ex1 * g_z2[(size_t)s1 * 30 + c];
        }
    }
    if (p < end) {
        int s0 = g_csr_src[p];
        float e0 = g_es2[s0 * HH + h] + ed;
        e0 = (e0 > 0.f) ? e0 : 0.2f * e0;
        float ex0 = __expf(e0);
        den += ex0;
        if (c < 30) acc0 += ex0 * g_z2[(size_t)s0 * 30 + c];
    }
    float s = (acc0 + acc1) / (den + 1e-16f);
    float s10 = __shfl_down_sync(0xffffffffu, s, 10);
    float s20 = __shfl_down_sync(0xffffffffu, s, 20);
    float t = (s + s10 + s20) * (1.f / 3.f);
    float tm = (lane < 10) ? t : -INFINITY;
    #pragma unroll
    for (int o = 8; o; o >>= 1)
        tm = fmaxf(tm, __shfl_xor_sync(0xffffffffu, tm, o, 16));
    float te = (lane < 10) ? __expf(t - tm) : 0.f;
    #pragma unroll
    for (int o = 8; o; o >>= 1)
        te += __shfl_xor_sync(0xffffffffu, te, o, 16);
    float lse = __logf(te) + tm;
    if (lane < 10) {
        out[(size_t)n * DOUT + lane] = t;
        out[half + (size_t)n * DOUT + lane] = t - lse;
    }
}

// ---------------- launcher --------------------------------------------------
extern "C" void kernel_launch(void* const* d_in, const int* in_sizes, int n_in,
                              void* d_out, int out_size) {
    const float* x   = (const float*)d_in[0];
    const int*   ei  = (const int*)d_in[1];
    const float* W1  = (const float*)d_in[2];
    const float* as1 = (const float*)d_in[3];
    const float* ad1 = (const float*)d_in[4];
    const float* W2  = (const float*)d_in[5];
    const float* as2 = (const float*)d_in[6];
    const float* ad2 = (const float*)d_in[7];
    float* out = (float*)d_out;
    int half = out_size / 2;

    // CSR build (graph shared by both layers)
    csr_zero<<<(NN + 255) / 256, 256>>>();
    csr_hist<<<(EE + 255) / 256, 256>>>(ei);
    csr_scan<<<1, 1024>>>();
    csr_scatter<<<(EE + 255) / 256, 256>>>(ei);

    // layer 1
    gemm1_tc<<<(NN + 127) / 128, 256>>>(x, W1);
    attn1_kernel<<<(NN * HH * 32 + 255) / 256, 256>>>(as1, ad1);
    agg1_kernel<<<NN, 192>>>();

    // layer 2
    gemm2_kernel<<<(NN + 63) / 64, 256>>>(W2);
    attn2_kernel<<<(NN * HH + 255) / 256, 256>>>(as2, ad2);
    agg2_kernel<<<(NN * 32 + 255) / 256, 256>>>(out, half);
}

// round 7
// speedup vs baseline: 1.4887x; 1.0493x over previous
#include <cuda_runtime.h>
#include <cuda_bf16.h>
#include <math.h>

// Problem constants (fixed-shape benchmark)
#define NN 50000
#define EE 800000
#define HH 3
#define DIN 256
#define DHID 64
#define DOUT 10

// ---------------- scratch (device globals; no allocation allowed) -----------
__device__ float g_z1[NN * HH * DHID];     // [N,192]  38.4 MB
__device__ float g_es1[NN * HH];
__device__ float g_ed1[NN * HH];
__device__ float g_h[NN * DHID];           // 12.8 MB
__device__ float g_z2[NN * HH * DOUT];     // [N,30]
__device__ float g_es2[NN * HH];
__device__ float g_ed2[NN * HH];
// CSR (by dst), shared across both layers
__device__ int g_deg[NN];
__device__ int g_ptr[NN + 1];
__device__ int g_cursor[NN];
__device__ int g_csr_src[EE];

// ---------------- helpers ---------------------------------------------------
__device__ __forceinline__ unsigned int f2tf32(float f) {
    unsigned int r;
    asm("cvt.rna.tf32.f32 %0, %1;" : "=r"(r) : "f"(f));
    return r;
}

__device__ __forceinline__ void mma_tf32(float* c, const unsigned int* a,
                                         const unsigned int* b) {
    asm volatile(
        "mma.sync.aligned.m16n8k8.row.col.f32.tf32.tf32.f32 "
        "{%0,%1,%2,%3}, {%4,%5,%6,%7}, {%8,%9}, {%0,%1,%2,%3};"
        : "+f"(c[0]), "+f"(c[1]), "+f"(c[2]), "+f"(c[3])
        : "r"(a[0]), "r"(a[1]), "r"(a[2]), "r"(a[3]), "r"(b[0]), "r"(b[1]));
}

// ---------------- CSR build --------------------------------------------------
__global__ void csr_zero() {
    int i = blockIdx.x * blockDim.x + threadIdx.x;
    if (i < NN) g_deg[i] = 0;
}

__global__ void csr_hist(const int* __restrict__ ei) {
    int e = blockIdx.x * blockDim.x + threadIdx.x;
    if (e >= EE) return;
    atomicAdd(&g_deg[ei[EE + e]], 1);
}

// single-block exclusive scan over g_deg -> g_ptr ; also cursor = ptr
__global__ void csr_scan() {
    __shared__ int part[1024];
    const int PER = (NN + 1023) / 1024;   // 49
    int t = threadIdx.x;
    int base = t * PER;
    int sum = 0;
    #pragma unroll 4
    for (int i = 0; i < PER; i++) {
        int idx = base + i;
        if (idx < NN) sum += g_deg[idx];
    }
    part[t] = sum;
    __syncthreads();
    for (int o = 1; o < 1024; o <<= 1) {
        int v = (t >= o) ? part[t - o] : 0;
        __syncthreads();
        part[t] += v;
        __syncthreads();
    }
    int off = (t == 0) ? 0 : part[t - 1];   // exclusive
    for (int i = 0; i < PER; i++) {
        int idx = base + i;
        if (idx < NN) {
            g_ptr[idx] = off;
            g_cursor[idx] = off;
            off += g_deg[idx];
        }
    }
    if (t == 1023) g_ptr[NN] = off;
}

__global__ void csr_scatter(const int* __restrict__ ei) {
    int e = blockIdx.x * blockDim.x + threadIdx.x;
    if (e >= EE) return;
    int src = ei[e], dst = ei[EE + e];
    int pos = atomicAdd(&g_cursor[dst], 1);
    g_csr_src[pos] = src;
}

// ---------------- GEMM1 (tensor cores, tf32): z1 = x @ Wcat -----------------
// BM=128, BN=192, BK=16, 256 threads = 8 warps (4M x 2N), warp tile 32x96.
// Register-staged double buffering: next K-tile LDGs issued before compute.
__global__ void __launch_bounds__(256) gemm1_tc(const float* __restrict__ x,
                                                const float* __restrict__ W1) {
    __shared__ unsigned int As[128][20];    // [m][k], pad 16->20
    __shared__ unsigned int Bs[16][196];    // [k][n=192], pad
    const int m0 = blockIdx.x * 128;
    const int tid = threadIdx.x;
    const int wid = tid >> 5, lane = tid & 31;
    const int warp_m = wid >> 1;            // 0..3 -> 32 rows each
    const int warp_n = wid & 1;             // 0..1 -> 96 cols each
    const int lr = lane >> 2;               // 0..7
    const int lc = lane & 3;                // 0..3

    float acc[2][12][4];
    #pragma unroll
    for (int mt = 0; mt < 2; mt++)
        #pragma unroll
        for (int nt = 0; nt < 12; nt++)
            #pragma unroll
            for (int q = 0; q < 4; q++) acc[mt][nt][q] = 0.f;

    float4 ra[2], rb[3];

    // A loader mapping: i = tid + r*256 -> row=i>>2, q=i&3
    // B loader mapping: i = tid + r*256 -> k=i/48, col=(i%48)*4
    #define LOAD_TILE(kk)                                                     \
        {                                                                     \
            _Pragma("unroll")                                                 \
            for (int r = 0; r < 2; r++) {                                     \
                int i = tid + r * 256;                                        \
                int row = i >> 2, q = i & 3;                                  \
                int gr = m0 + row;                                            \
                ra[r] = (gr < NN)                                             \
                    ? *(const float4*)(x + (size_t)gr * DIN + (kk) + q * 4)   \
                    : make_float4(0.f, 0.f, 0.f, 0.f);                        \
            }                                                                 \
            _Pragma("unroll")                                                 \
            for (int r = 0; r < 3; r++) {                                     \
                int i = tid + r * 256;                                        \
                int k = i / 48, cc = (i % 48) * 4;                            \
                int h = cc >> 6, j = cc & 63;                                 \
                rb[r] = *(const float4*)(W1 + h * (DIN * DHID)                \
                                          + (size_t)((kk) + k) * DHID + j);   \
            }                                                                 \
        }

    #define STORE_TILE()                                                      \
        {                                                                     \
            _Pragma("unroll")                                                 \
            for (int r = 0; r < 2; r++) {                                     \
                int i = tid + r * 256;                                        \
                int row = i >> 2, q = i & 3;                                  \
                As[row][q * 4 + 0] = f2tf32(ra[r].x);                         \
                As[row][q * 4 + 1] = f2tf32(ra[r].y);                         \
                As[row][q * 4 + 2] = f2tf32(ra[r].z);                         \
                As[row][q * 4 + 3] = f2tf32(ra[r].w);                         \
            }                                                                 \
            _Pragma("unroll")                                                 \
            for (int r = 0; r < 3; r++) {                                     \
                int i = tid + r * 256;                                        \
                int k = i / 48, cc = (i % 48) * 4;                            \
                Bs[k][cc + 0] = f2tf32(rb[r].x);                              \
                Bs[k][cc + 1] = f2tf32(rb[r].y);                              \
                Bs[k][cc + 2] = f2tf32(rb[r].z);                              \
                Bs[k][cc + 3] = f2tf32(rb[r].w);                              \
            }                                                                 \
        }

    LOAD_TILE(0);
    STORE_TILE();
    __syncthreads();

    for (int kk = 0; kk < DIN; kk += 16) {
        bool more = (kk + 16 < DIN);
        if (more) LOAD_TILE(kk + 16);
        // ---- compute ----
        #pragma unroll
        for (int ks = 0; ks < 2; ks++) {
            int kb = ks * 8;
            unsigned int afrag[2][4];
            #pragma unroll
            for (int mt = 0; mt < 2; mt++) {
                int m = warp_m * 32 + mt * 16 + lr;
                afrag[mt][0] = As[m][kb + lc];
                afrag[mt][1] = As[m + 8][kb + lc];
                afrag[mt][2] = As[m][kb + lc + 4];
                afrag[mt][3] = As[m + 8][kb + lc + 4];
            }
            #pragma unroll
            for (int nt = 0; nt < 12; nt++) {
                int n = warp_n * 96 + nt * 8 + lr;
                unsigned int bfrag[2];
                bfrag[0] = Bs[kb + lc][n];
                bfrag[1] = Bs[kb + lc + 4][n];
                mma_tf32(acc[0][nt], afrag[0], bfrag);
                mma_tf32(acc[1][nt], afrag[1], bfrag);
            }
        }
        if (more) {
            __syncthreads();
            STORE_TILE();
            __syncthreads();
        }
    }
    // ---- epilogue ----
    #pragma unroll
    for (int mt = 0; mt < 2; mt++) {
        int row0 = m0 + warp_m * 32 + mt * 16 + lr;
        #pragma unroll
        for (int nt = 0; nt < 12; nt++) {
            int col = warp_n * 96 + nt * 8 + lc * 2;
            if (row0 < NN) {
                g_z1[(size_t)row0 * 192 + col]     = acc[mt][nt][0];
                g_z1[(size_t)row0 * 192 + col + 1] = acc[mt][nt][1];
            }
            if (row0 + 8 < NN) {
                g_z1[(size_t)(row0 + 8) * 192 + col]     = acc[mt][nt][2];
                g_z1[(size_t)(row0 + 8) * 192 + col + 1] = acc[mt][nt][3];
            }
        }
    }
    #undef LOAD_TILE
    #undef STORE_TILE
}

// ---------------- attention coefficients layer 1 (warp per (n,h)) ----------
__global__ void attn1_kernel(const float* __restrict__ as1,
                             const float* __restrict__ ad1) {
    int gw = (blockIdx.x * blockDim.x + threadIdx.x) >> 5;
    int lane = threadIdx.x & 31;
    if (gw >= NN * HH) return;
    int n = gw / HH, h = gw % HH;
    const float* z = g_z1 + (size_t)n * (HH * DHID) + h * DHID;
    const float* ws = as1 + h * DHID;
    const float* wd = ad1 + h * DHID;
    float vs = z[lane] * ws[lane] + z[lane + 32] * ws[lane + 32];
    float vd = z[lane] * wd[lane] + z[lane + 32] * wd[lane + 32];
    #pragma unroll
    for (int o = 16; o; o >>= 1) {
        vs += __shfl_xor_sync(0xffffffffu, vs, o);
        vd += __shfl_xor_sync(0xffffffffu, vd, o);
    }
    if (lane == 0) { g_es1[gw] = vs; g_ed1[gw] = vd; }
}

// ---------------- layer-1 fused: softmax-weight + gather-agg + mean + ELU ---
// one block (192 threads) per dst node; per-chunk ex staged in shared once
__global__ void agg1_kernel() {
    int n = blockIdx.x;
    int c = threadIdx.x;            // 0..191
    int h = c >> 6;
    int j64 = c & 63;
    __shared__ int s_src[64];
    __shared__ float s_ex[192];     // [h*64 + j]
    __shared__ float s_red[192];
    int beg = g_ptr[n], end = g_ptr[n + 1];
    float ed = g_ed1[n * HH + h];
    float acc0 = 0.f, acc1 = 0.f, den0 = 0.f, den1 = 0.f;
    for (int base = beg; base < end; base += 64) {
        int cnt = min(64, end - base);
        __syncthreads();
        if (c < cnt) s_src[c] = g_csr_src[base + c];
        __syncthreads();
        if (j64 < cnt) {
            float e = g_es1[s_src[j64] * HH + h] + ed;
            e = (e > 0.f) ? e : 0.2f * e;
            s_ex[h * 64 + j64] = __expf(e);
        }
        __syncthreads();
        int p2 = cnt & ~1;
        const float* exb = &s_ex[h * 64];
        for (int j = 0; j < p2; j += 2) {
            int s0 = s_src[j], s1 = s_src[j + 1];
            float ex0 = exb[j], ex1 = exb[j + 1];
            float z0 = g_z1[(size_t)s0 * 192 + c];
            float z1v = g_z1[(size_t)s1 * 192 + c];
            den0 += ex0; den1 += ex1;
            acc0 += ex0 * z0;
            acc1 += ex1 * z1v;
        }
        if (p2 < cnt) {
            int s0 = s_src[p2];
            float ex0 = exb[p2];
            den0 += ex0;
            acc0 += ex0 * g_z1[(size_t)s0 * 192 + c];
        }
    }
    s_red[c] = (acc0 + acc1) / (den0 + den1 + 1e-16f);
    __syncthreads();
    if (c < 64) {
        float v = (s_red[c] + s_red[c + 64] + s_red[c + 128]) * (1.f / 3.f);
        g_h[n * DHID + c] = (v > 0.f) ? v : expm1f(v);
    }
}

// ---------------- GEMM2: z2[n, h*10+o] = sum_k h[n,k] * W2[h,k,o] -----------
__global__ void gemm2_kernel(const float* __restrict__ W2) {
    __shared__ float hs[64][65];
    __shared__ float Ws[HH * DHID * DOUT];   // 1920
    int n0 = blockIdx.x * 64;
    int tid = threadIdx.x;
    for (int i = tid; i < HH * DHID * DOUT; i += 256) Ws[i] = W2[i];
    for (int i = tid; i < 64 * 64; i += 256) {
        int nl = i >> 6, d = i & 63;
        int gn = n0 + nl;
        hs[nl][d] = (gn < NN) ? g_h[(size_t)gn * DHID + d] : 0.f;
    }
    __syncthreads();
    for (int i = tid; i < 64 * HH * DOUT; i += 256) {
        int nl = i / 30, c = i - nl * 30;
        int gn = n0 + nl;
        if (gn >= NN) continue;
        int h = c / DOUT, o = c - h * DOUT;
        const float* w = Ws + h * (DHID * DOUT) + o;
        float s = 0.f;
        #pragma unroll
        for (int k = 0; k < DHID; k++) s += hs[nl][k] * w[k * DOUT];
        g_z2[(size_t)gn * (HH * DOUT) + c] = s;
    }
}

__global__ void attn2_kernel(const float* __restrict__ as2,
                             const float* __restrict__ ad2) {
    int idx = blockIdx.x * blockDim.x + threadIdx.x;
    if (idx >= NN * HH) return;
    int n = idx / HH, h = idx - n * HH;
    const float* z = g_z2 + (size_t)n * (HH * DOUT) + h * DOUT;
    float vs = 0.f, vd = 0.f;
    #pragma unroll
    for (int o = 0; o < DOUT; o++) {
        vs += z[o] * as2[h * DOUT + o];
        vd += z[o] * ad2[h * DOUT + o];
    }
    g_es2[idx] = vs; g_ed2[idx] = vd;
}

// ---------------- layer-2 fused: gather-agg + mean + log_softmax ------------
// one warp per dst node
__global__ void agg2_kernel(float* __restrict__ out, int half) {
    int warp = (blockIdx.x * blockDim.x + threadIdx.x) >> 5;
    int lane = threadIdx.x & 31;
    if (warp >= NN) return;
    int n = warp;
    int c = lane;                   // 0..29 active
    int h = (c < 30) ? (c / DOUT) : 0;
    float ed = g_ed2[n * HH + h];
    int beg = g_ptr[n], end = g_ptr[n + 1];
    float acc0 = 0.f, acc1 = 0.f, den = 0.f;
    int p = beg;
    for (; p + 1 < end; p += 2) {
        int s0 = g_csr_src[p], s1 = g_csr_src[p + 1];
        float e0 = g_es2[s0 * HH + h] + ed;
        float e1 = g_es2[s1 * HH + h] + ed;
        e0 = (e0 > 0.f) ? e0 : 0.2f * e0;
        e1 = (e1 > 0.f) ? e1 : 0.2f * e1;
        float ex0 = __expf(e0), ex1 = __expf(e1);
        den += ex0 + ex1;
        if (c < 30) {
            acc0 += ex0 * g_z2[(size_t)s0 * 30 + c];
            acc1 += ex1 * g_z2[(size_t)s1 * 30 + c];
        }
    }
    if (p < end) {
        int s0 = g_csr_src[p];
        float e0 = g_es2[s0 * HH + h] + ed;
        e0 = (e0 > 0.f) ? e0 : 0.2f * e0;
        float ex0 = __expf(e0);
        den += ex0;
        if (c < 30) acc0 += ex0 * g_z2[(size_t)s0 * 30 + c];
    }
    float s = (acc0 + acc1) / (den + 1e-16f);
    float s10 = __shfl_down_sync(0xffffffffu, s, 10);
    float s20 = __shfl_down_sync(0xffffffffu, s, 20);
    float t = (s + s10 + s20) * (1.f / 3.f);
    float tm = (lane < 10) ? t : -INFINITY;
    #pragma unroll
    for (int o = 8; o; o >>= 1)
        tm = fmaxf(tm, __shfl_xor_sync(0xffffffffu, tm, o, 16));
    float te = (lane < 10) ? __expf(t - tm) : 0.f;
    #pragma unroll
    for (int o = 8; o; o >>= 1)
        te += __shfl_xor_sync(0xffffffffu, te, o, 16);
    float lse = __logf(te) + tm;
    if (lane < 10) {
        out[(size_t)n * DOUT + lane] = t;
        out[half + (size_t)n * DOUT + lane] = t - lse;
    }
}

// ---------------- launcher --------------------------------------------------
extern "C" void kernel_launch(void* const* d_in, const int* in_sizes, int n_in,
                              void* d_out, int out_size) {
    const float* x   = (const float*)d_in[0];
    const int*   ei  = (const int*)d_in[1];
    const float* W1  = (const float*)d_in[2];
    const float* as1 = (const float*)d_in[3];
    const float* ad1 = (const float*)d_in[4];
    const float* W2  = (const float*)d_in[5];
    const float* as2 = (const float*)d_in[6];
    const float* ad2 = (const float*)d_in[7];
    float* out = (float*)d_out;
    int half = out_size / 2;

    // CSR build (graph shared by both layers)
    csr_zero<<<(NN + 255) / 256, 256>>>();
    csr_hist<<<(EE + 255) / 256, 256>>>(ei);
    csr_scan<<<1, 1024>>>();
    csr_scatter<<<(EE + 255) / 256, 256>>>(ei);

    // layer 1
    gemm1_tc<<<(NN + 127) / 128, 256>>>(x, W1);
    attn1_kernel<<<(NN * HH * 32 + 255) / 256, 256>>>(as1, ad1);
    agg1_kernel<<<NN, 192>>>();

    // layer 2
    gemm2_kernel<<<(NN + 63) / 64, 256>>>(W2);
    attn2_kernel<<<(NN * HH + 255) / 256, 256>>>(as2, ad2);
    agg2_kernel<<<(NN * 32 + 255) / 256, 256>>>(out, half);
}

// round 8
// speedup vs baseline: 1.5779x; 1.0599x over previous
#include <cuda_runtime.h>
#include <cuda_bf16.h>
#include <math.h>

// Problem constants (fixed-shape benchmark)
#define NN 50000
#define EE 800000
#define HH 3
#define DIN 256
#define DHID 64
#define DOUT 10

// ---------------- scratch (device globals; no allocation allowed) -----------
__device__ float g_z1[NN * HH * DHID];     // [N,192]  38.4 MB
__device__ float g_es1[NN * HH];
__device__ float g_ed1[NN * HH];
__device__ float g_h[NN * DHID];           // 12.8 MB
__device__ float g_z2[NN * HH * DOUT];     // [N,30]
__device__ float g_es2[NN * HH];
__device__ float g_ed2[NN * HH];
// CSR (by dst), shared across both layers
__device__ int g_deg[NN];
__device__ int g_ptr[NN + 1];
__device__ int g_cursor[NN];
__device__ int g_csr_src[EE];

// ---------------- side stream for CSR-build overlap (created at load) -------
struct StreamHolder {
    cudaStream_t s2 = nullptr;
    cudaEvent_t e1 = nullptr, e2 = nullptr;
    bool ok = false;
    StreamHolder() {
        if (cudaStreamCreateWithFlags(&s2, cudaStreamNonBlocking) == cudaSuccess &&
            cudaEventCreateWithFlags(&e1, cudaEventDisableTiming) == cudaSuccess &&
            cudaEventCreateWithFlags(&e2, cudaEventDisableTiming) == cudaSuccess)
            ok = true;
    }
};
static StreamHolder g_sh;

// ---------------- helpers ---------------------------------------------------
__device__ __forceinline__ unsigned int f2tf32(float f) {
    unsigned int r;
    asm("cvt.rna.tf32.f32 %0, %1;" : "=r"(r) : "f"(f));
    return r;
}

__device__ __forceinline__ void mma_tf32(float* c, const unsigned int* a,
                                         const unsigned int* b) {
    asm volatile(
        "mma.sync.aligned.m16n8k8.row.col.f32.tf32.tf32.f32 "
        "{%0,%1,%2,%3}, {%4,%5,%6,%7}, {%8,%9}, {%0,%1,%2,%3};"
        : "+f"(c[0]), "+f"(c[1]), "+f"(c[2]), "+f"(c[3])
        : "r"(a[0]), "r"(a[1]), "r"(a[2]), "r"(a[3]), "r"(b[0]), "r"(b[1]));
}

// ---------------- CSR build --------------------------------------------------
__global__ void csr_zero() {
    int i = blockIdx.x * blockDim.x + threadIdx.x;
    if (i < NN) g_deg[i] = 0;
}

__global__ void csr_hist(const int* __restrict__ ei) {
    int e = blockIdx.x * blockDim.x + threadIdx.x;
    if (e >= EE) return;
    atomicAdd(&g_deg[ei[EE + e]], 1);
}

// single-block exclusive scan over g_deg -> g_ptr ; also cursor = ptr
__global__ void csr_scan() {
    __shared__ int part[1024];
    const int PER = (NN + 1023) / 1024;   // 49
    int t = threadIdx.x;
    int base = t * PER;
    int sum = 0;
    #pragma unroll 4
    for (int i = 0; i < PER; i++) {
        int idx = base + i;
        if (idx < NN) sum += g_deg[idx];
    }
    part[t] = sum;
    __syncthreads();
    for (int o = 1; o < 1024; o <<= 1) {
        int v = (t >= o) ? part[t - o] : 0;
        __syncthreads();
        part[t] += v;
        __syncthreads();
    }
    int off = (t == 0) ? 0 : part[t - 1];   // exclusive
    for (int i = 0; i < PER; i++) {
        int idx = base + i;
        if (idx < NN) {
            g_ptr[idx] = off;
            g_cursor[idx] = off;
            off += g_deg[idx];
        }
    }
    if (t == 1023) g_ptr[NN] = off;
}

__global__ void csr_scatter(const int* __restrict__ ei) {
    int e = blockIdx.x * blockDim.x + threadIdx.x;
    if (e >= EE) return;
    int src = ei[e], dst = ei[EE + e];
    int pos = atomicAdd(&g_cursor[dst], 1);
    g_csr_src[pos] = src;
}

// ---------------- GEMM1 (tensor cores, tf32): z1 = x @ Wcat -----------------
// BM=128, BN=192, BK=16, 256 threads = 8 warps (4M x 2N), warp tile 32x96.
// Double-buffered smem + register staging: one syncthreads per K-iter.
__global__ void __launch_bounds__(256) gemm1_tc(const float* __restrict__ x,
                                                const float* __restrict__ W1) {
    __shared__ unsigned int As[2][128][20];    // 2 x 10 KB
    __shared__ unsigned int Bs[2][16][196];    // 2 x 12.25 KB  (total 45.5 KB)
    const int m0 = blockIdx.x * 128;
    const int tid = threadIdx.x;
    const int wid = tid >> 5, lane = tid & 31;
    const int warp_m = wid >> 1;            // 0..3 -> 32 rows each
    const int warp_n = wid & 1;             // 0..1 -> 96 cols each
    const int lr = lane >> 2;               // 0..7
    const int lc = lane & 3;                // 0..3

    float acc[2][12][4];
    #pragma unroll
    for (int mt = 0; mt < 2; mt++)
        #pragma unroll
        for (int nt = 0; nt < 12; nt++)
            #pragma unroll
            for (int q = 0; q < 4; q++) acc[mt][nt][q] = 0.f;

    float4 ra[2], rb[3];

    #define LOAD_TILE(kk)                                                     \
        {                                                                     \
            _Pragma("unroll")                                                 \
            for (int r = 0; r < 2; r++) {                                     \
                int i = tid + r * 256;                                        \
                int row = i >> 2, q = i & 3;                                  \
                int gr = m0 + row;                                            \
                ra[r] = (gr < NN)                                             \
                    ? *(const float4*)(x + (size_t)gr * DIN + (kk) + q * 4)   \
                    : make_float4(0.f, 0.f, 0.f, 0.f);                        \
            }                                                                 \
            _Pragma("unroll")                                                 \
            for (int r = 0; r < 3; r++) {                                     \
                int i = tid + r * 256;                                        \
                int k = i / 48, cc = (i % 48) * 4;                            \
                int h = cc >> 6, j = cc & 63;                                 \
                rb[r] = *(const float4*)(W1 + h * (DIN * DHID)                \
                                          + (size_t)((kk) + k) * DHID + j);   \
            }                                                                 \
        }

    #define STORE_TILE(p)                                                     \
        {                                                                     \
            _Pragma("unroll")                                                 \
            for (int r = 0; r < 2; r++) {                                     \
                int i = tid + r * 256;                                        \
                int row = i >> 2, q = i & 3;                                  \
                As[p][row][q * 4 + 0] = f2tf32(ra[r].x);                      \
                As[p][row][q * 4 + 1] = f2tf32(ra[r].y);                      \
                As[p][row][q * 4 + 2] = f2tf32(ra[r].z);                      \
                As[p][row][q * 4 + 3] = f2tf32(ra[r].w);                      \
            }                                                                 \
            _Pragma("unroll")                                                 \
            for (int r = 0; r < 3; r++) {                                     \
                int i = tid + r * 256;                                        \
                int k = i / 48, cc = (i % 48) * 4;                            \
                Bs[p][k][cc + 0] = f2tf32(rb[r].x);                           \
                Bs[p][k][cc + 1] = f2tf32(rb[r].y);                           \
                Bs[p][k][cc + 2] = f2tf32(rb[r].z);                           \
                Bs[p][k][cc + 3] = f2tf32(rb[r].w);                           \
            }                                                                 \
        }

    LOAD_TILE(0);
    STORE_TILE(0);
    __syncthreads();

    int p = 0;
    for (int kk = 0; kk < DIN; kk += 16) {
        bool more = (kk + 16 < DIN);
        if (more) LOAD_TILE(kk + 16);
        // ---- compute from buffer p ----
        #pragma unroll
        for (int ks = 0; ks < 2; ks++) {
            int kb = ks * 8;
            unsigned int afrag[2][4];
            #pragma unroll
            for (int mt = 0; mt < 2; mt++) {
                int m = warp_m * 32 + mt * 16 + lr;
                afrag[mt][0] = As[p][m][kb + lc];
                afrag[mt][1] = As[p][m + 8][kb + lc];
                afrag[mt][2] = As[p][m][kb + lc + 4];
                afrag[mt][3] = As[p][m + 8][kb + lc + 4];
            }
            #pragma unroll
            for (int nt = 0; nt < 12; nt++) {
                int n = warp_n * 96 + nt * 8 + lr;
                unsigned int bfrag[2];
                bfrag[0] = Bs[p][kb + lc][n];
                bfrag[1] = Bs[p][kb + lc + 4][n];
                mma_tf32(acc[0][nt], afrag[0], bfrag);
                mma_tf32(acc[1][nt], afrag[1], bfrag);
            }
        }
        if (more) {
            STORE_TILE(p ^ 1);
            __syncthreads();
            p ^= 1;
        }
    }
    // ---- epilogue ----
    #pragma unroll
    for (int mt = 0; mt < 2; mt++) {
        int row0 = m0 + warp_m * 32 + mt * 16 + lr;
        #pragma unroll
        for (int nt = 0; nt < 12; nt++) {
            int col = warp_n * 96 + nt * 8 + lc * 2;
            if (row0 < NN) {
                g_z1[(size_t)row0 * 192 + col]     = acc[mt][nt][0];
                g_z1[(size_t)row0 * 192 + col + 1] = acc[mt][nt][1];
            }
            if (row0 + 8 < NN) {
                g_z1[(size_t)(row0 + 8) * 192 + col]     = acc[mt][nt][2];
                g_z1[(size_t)(row0 + 8) * 192 + col + 1] = acc[mt][nt][3];
            }
        }
    }
    #undef LOAD_TILE
    #undef STORE_TILE
}

// ---------------- attention coefficients layer 1 (warp per (n,h)) ----------
__global__ void attn1_kernel(const float* __restrict__ as1,
                             const float* __restrict__ ad1) {
    int gw = (blockIdx.x * blockDim.x + threadIdx.x) >> 5;
    int lane = threadIdx.x & 31;
    if (gw >= NN * HH) return;
    int n = gw / HH, h = gw % HH;
    const float* z = g_z1 + (size_t)n * (HH * DHID) + h * DHID;
    const float* ws = as1 + h * DHID;
    const float* wd = ad1 + h * DHID;
    float vs = z[lane] * ws[lane] + z[lane + 32] * ws[lane + 32];
    float vd = z[lane] * wd[lane] + z[lane + 32] * wd[lane + 32];
    #pragma unroll
    for (int o = 16; o; o >>= 1) {
        vs += __shfl_xor_sync(0xffffffffu, vs, o);
        vd += __shfl_xor_sync(0xffffffffu, vd, o);
    }
    if (lane == 0) { g_es1[gw] = vs; g_ed1[gw] = vd; }
}

// ---------------- layer-1 fused: softmax-weight + gather-agg + mean + ELU ---
// one block (192 threads) per dst node; per-chunk ex staged in shared once
__global__ void agg1_kernel() {
    int n = blockIdx.x;
    int c = threadIdx.x;            // 0..191
    int h = c >> 6;
    int j64 = c & 63;
    __shared__ int s_src[64];
    __shared__ float s_ex[192];     // [h*64 + j]
    __shared__ float s_red[192];
    int beg = g_ptr[n], end = g_ptr[n + 1];
    float ed = g_ed1[n * HH + h];
    float acc0 = 0.f, acc1 = 0.f, den0 = 0.f, den1 = 0.f;
    for (int base = beg; base < end; base += 64) {
        int cnt = min(64, end - base);
        __syncthreads();
        if (c < cnt) s_src[c] = g_csr_src[base + c];
        __syncthreads();
        if (j64 < cnt) {
            float e = g_es1[s_src[j64] * HH + h] + ed;
            e = (e > 0.f) ? e : 0.2f * e;
            s_ex[h * 64 + j64] = __expf(e);
        }
        __syncthreads();
        const float* exb = &s_ex[h * 64];
        int p4 = cnt & ~3;
        for (int j = 0; j < p4; j += 4) {
            int s0 = s_src[j],     s1 = s_src[j + 1];
            int s2 = s_src[j + 2], s3 = s_src[j + 3];
            float z0 = g_z1[(size_t)s0 * 192 + c];
            float z1v = g_z1[(size_t)s1 * 192 + c];
            float z2v = g_z1[(size_t)s2 * 192 + c];
            float z3v = g_z1[(size_t)s3 * 192 + c];
            float ex0 = exb[j], ex1 = exb[j + 1];
            float ex2 = exb[j + 2], ex3 = exb[j + 3];
            den0 += ex0 + ex2; den1 += ex1 + ex3;
            acc0 += ex0 * z0 + ex2 * z2v;
            acc1 += ex1 * z1v + ex3 * z3v;
        }
        for (int j = p4; j < cnt; j++) {
            int s0 = s_src[j];
            float ex0 = exb[j];
            den0 += ex0;
            acc0 += ex0 * g_z1[(size_t)s0 * 192 + c];
        }
    }
    s_red[c] = (acc0 + acc1) / (den0 + den1 + 1e-16f);
    __syncthreads();
    if (c < 64) {
        float v = (s_red[c] + s_red[c + 64] + s_red[c + 128]) * (1.f / 3.f);
        g_h[n * DHID + c] = (v > 0.f) ? v : expm1f(v);
    }
}

// ---------------- GEMM2: z2[n, h*10+o] = sum_k h[n,k] * W2[h,k,o] -----------
__global__ void gemm2_kernel(const float* __restrict__ W2) {
    __shared__ float hs[64][65];
    __shared__ float Ws[HH * DHID * DOUT];   // 1920
    int n0 = blockIdx.x * 64;
    int tid = threadIdx.x;
    for (int i = tid; i < HH * DHID * DOUT; i += 256) Ws[i] = W2[i];
    for (int i = tid; i < 64 * 64; i += 256) {
        int nl = i >> 6, d = i & 63;
        int gn = n0 + nl;
        hs[nl][d] = (gn < NN) ? g_h[(size_t)gn * DHID + d] : 0.f;
    }
    __syncthreads();
    for (int i = tid; i < 64 * HH * DOUT; i += 256) {
        int nl = i / 30, c = i - nl * 30;
        int gn = n0 + nl;
        if (gn >= NN) continue;
        int h = c / DOUT, o = c - h * DOUT;
        const float* w = Ws + h * (DHID * DOUT) + o;
        float s = 0.f;
        #pragma unroll
        for (int k = 0; k < DHID; k++) s += hs[nl][k] * w[k * DOUT];
        g_z2[(size_t)gn * (HH * DOUT) + c] = s;
    }
}

__global__ void attn2_kernel(const float* __restrict__ as2,
                             const float* __restrict__ ad2) {
    int idx = blockIdx.x * blockDim.x + threadIdx.x;
    if (idx >= NN * HH) return;
    int n = idx / HH, h = idx - n * HH;
    const float* z = g_z2 + (size_t)n * (HH * DOUT) + h * DOUT;
    float vs = 0.f, vd = 0.f;
    #pragma unroll
    for (int o = 0; o < DOUT; o++) {
        vs += z[o] * as2[h * DOUT + o];
        vd += z[o] * ad2[h * DOUT + o];
    }
    g_es2[idx] = vs; g_ed2[idx] = vd;
}

// ---------------- layer-2 fused: gather-agg + mean + log_softmax ------------
// one warp per dst node
__global__ void agg2_kernel(float* __restrict__ out, int half) {
    int warp = (blockIdx.x * blockDim.x + threadIdx.x) >> 5;
    int lane = threadIdx.x & 31;
    if (warp >= NN) return;
    int n = warp;
    int c = lane;                   // 0..29 active
    int h = (c < 30) ? (c / DOUT) : 0;
    float ed = g_ed2[n * HH + h];
    int beg = g_ptr[n], end = g_ptr[n + 1];
    float acc0 = 0.f, acc1 = 0.f, den = 0.f;
    int p = beg;
    for (; p + 1 < end; p += 2) {
        int s0 = g_csr_src[p], s1 = g_csr_src[p + 1];
        float e0 = g_es2[s0 * HH + h] + ed;
        float e1 = g_es2[s1 * HH + h] + ed;
        e0 = (e0 > 0.f) ? e0 : 0.2f * e0;
        e1 = (e1 > 0.f) ? e1 : 0.2f * e1;
        float ex0 = __expf(e0), ex1 = __expf(e1);
        den += ex0 + ex1;
        if (c < 30) {
            acc0 += ex0 * g_z2[(size_t)s0 * 30 + c];
            acc1 += ex1 * g_z2[(size_t)s1 * 30 + c];
        }
    }
    if (p < end) {
        int s0 = g_csr_src[p];
        float e0 = g_es2[s0 * HH + h] + ed;
        e0 = (e0 > 0.f) ? e0 : 0.2f * e0;
        float ex0 = __expf(e0);
        den += ex0;
        if (c < 30) acc0 += ex0 * g_z2[(size_t)s0 * 30 + c];
    }
    float s = (acc0 + acc1) / (den + 1e-16f);
    float s10 = __shfl_down_sync(0xffffffffu, s, 10);
    float s20 = __shfl_down_sync(0xffffffffu, s, 20);
    float t = (s + s10 + s20) * (1.f / 3.f);
    float tm = (lane < 10) ? t : -INFINITY;
    #pragma unroll
    for (int o = 8; o; o >>= 1)
        tm = fmaxf(tm, __shfl_xor_sync(0xffffffffu, tm, o, 16));
    float te = (lane < 10) ? __expf(t - tm) : 0.f;
    #pragma unroll
    for (int o = 8; o; o >>= 1)
        te += __shfl_xor_sync(0xffffffffu, te, o, 16);
    float lse = __logf(te) + tm;
    if (lane < 10) {
        out[(size_t)n * DOUT + lane] = t;
        out[half + (size_t)n * DOUT + lane] = t - lse;
    }
}

// ---------------- launcher --------------------------------------------------
extern "C" void kernel_launch(void* const* d_in, const int* in_sizes, int n_in,
                              void* d_out, int out_size) {
    const float* x   = (const float*)d_in[0];
    const int*   ei  = (const int*)d_in[1];
    const float* W1  = (const float*)d_in[2];
    const float* as1 = (const float*)d_in[3];
    const float* ad1 = (const float*)d_in[4];
    const float* W2  = (const float*)d_in[5];
    const float* as2 = (const float*)d_in[6];
    const float* ad2 = (const float*)d_in[7];
    float* out = (float*)d_out;
    int half = out_size / 2;

    if (g_sh.ok) {
        // fork: CSR build on side stream, concurrent with gemm1+attn1
        cudaEventRecord(g_sh.e1, 0);
        cudaStreamWaitEvent(g_sh.s2, g_sh.e1, 0);
        csr_zero<<<(NN + 255) / 256, 256, 0, g_sh.s2>>>();
        csr_hist<<<(EE + 255) / 256, 256, 0, g_sh.s2>>>(ei);
        csr_scan<<<1, 1024, 0, g_sh.s2>>>();
        csr_scatter<<<(EE + 255) / 256, 256, 0, g_sh.s2>>>(ei);
        cudaEventRecord(g_sh.e2, g_sh.s2);

        gemm1_tc<<<(NN + 127) / 128, 256>>>(x, W1);
        attn1_kernel<<<(NN * HH * 32 + 255) / 256, 256>>>(as1, ad1);

        cudaStreamWaitEvent(0, g_sh.e2, 0);   // join before agg1
    } else {
        csr_zero<<<(NN + 255) / 256, 256>>>();
        csr_hist<<<(EE + 255) / 256, 256>>>(ei);
        csr_scan<<<1, 1024>>>();
        csr_scatter<<<(EE + 255) / 256, 256>>>(ei);
        gemm1_tc<<<(NN + 127) / 128, 256>>>(x, W1);
        attn1_kernel<<<(NN * HH * 32 + 255) / 256, 256>>>(as1, ad1);
    }

    agg1_kernel<<<NN, 192>>>();

    // layer 2
    gemm2_kernel<<<(NN + 63) / 64, 256>>>(W2);
    attn2_kernel<<<(NN * HH + 255) / 256, 256>>>(as2, ad2);
    agg2_kernel<<<(NN * 32 + 255) / 256, 256>>>(out, half);
}

// round 9
// speedup vs baseline: 1.8066x; 1.1449x over previous
#include <cuda_runtime.h>
#include <cuda_bf16.h>
#include <math.h>

// Problem constants (fixed-shape benchmark)
#define NN 50000
#define EE 800000
#define HH 3
#define DIN 256
#define DHID 64
#define DOUT 10

// ---------------- scratch (device globals; no allocation allowed) -----------
__device__ float g_z1[NN * HH * DHID];     // [N,192]  38.4 MB
__device__ float g_es1[NN * HH];
__device__ float g_ed1[NN * HH];
__device__ float g_h[NN * DHID];           // 12.8 MB
__device__ float g_z2[NN * HH * DOUT];     // [N,30]
__device__ float g_es2[NN * HH];
__device__ float g_ed2[NN * HH];
// CSR (by dst), shared across both layers
__device__ int g_deg[NN];
__device__ int g_ptr[NN + 1];
__device__ int g_cursor[NN];
__device__ int g_csr_src[EE];

// ---------------- side stream for CSR-build overlap (created at load) -------
struct StreamHolder {
    cudaStream_t s2 = nullptr;
    cudaEvent_t e1 = nullptr, e2 = nullptr;
    bool ok = false;
    StreamHolder() {
        if (cudaStreamCreateWithFlags(&s2, cudaStreamNonBlocking) == cudaSuccess &&
            cudaEventCreateWithFlags(&e1, cudaEventDisableTiming) == cudaSuccess &&
            cudaEventCreateWithFlags(&e2, cudaEventDisableTiming) == cudaSuccess)
            ok = true;
    }
};
static StreamHolder g_sh;

// ---------------- helpers ---------------------------------------------------
__device__ __forceinline__ unsigned int f2tf32(float f) {
    unsigned int r;
    asm("cvt.rna.tf32.f32 %0, %1;" : "=r"(r) : "f"(f));
    return r;
}

__device__ __forceinline__ void mma_tf32(float* c, const unsigned int* a,
                                         const unsigned int* b) {
    asm volatile(
        "mma.sync.aligned.m16n8k8.row.col.f32.tf32.tf32.f32 "
        "{%0,%1,%2,%3}, {%4,%5,%6,%7}, {%8,%9}, {%0,%1,%2,%3};"
        : "+f"(c[0]), "+f"(c[1]), "+f"(c[2]), "+f"(c[3])
        : "r"(a[0]), "r"(a[1]), "r"(a[2]), "r"(a[3]), "r"(b[0]), "r"(b[1]));
}

// ---------------- CSR build --------------------------------------------------
__global__ void csr_zero() {
    int i = blockIdx.x * blockDim.x + threadIdx.x;
    if (i < NN) g_deg[i] = 0;
}

__global__ void csr_hist(const int* __restrict__ ei) {
    int e = blockIdx.x * blockDim.x + threadIdx.x;
    if (e >= EE) return;
    atomicAdd(&g_deg[ei[EE + e]], 1);
}

// single-block exclusive scan over g_deg -> g_ptr ; also cursor = ptr
__global__ void csr_scan() {
    __shared__ int part[1024];
    const int PER = (NN + 1023) / 1024;   // 49
    int t = threadIdx.x;
    int base = t * PER;
    int sum = 0;
    #pragma unroll 4
    for (int i = 0; i < PER; i++) {
        int idx = base + i;
        if (idx < NN) sum += g_deg[idx];
    }
    part[t] = sum;
    __syncthreads();
    for (int o = 1; o < 1024; o <<= 1) {
        int v = (t >= o) ? part[t - o] : 0;
        __syncthreads();
        part[t] += v;
        __syncthreads();
    }
    int off = (t == 0) ? 0 : part[t - 1];   // exclusive
    for (int i = 0; i < PER; i++) {
        int idx = base + i;
        if (idx < NN) {
            g_ptr[idx] = off;
            g_cursor[idx] = off;
            off += g_deg[idx];
        }
    }
    if (t == 1023) g_ptr[NN] = off;
}

__global__ void csr_scatter(const int* __restrict__ ei) {
    int e = blockIdx.x * blockDim.x + threadIdx.x;
    if (e >= EE) return;
    int src = ei[e], dst = ei[EE + e];
    int pos = atomicAdd(&g_cursor[dst], 1);
    g_csr_src[pos] = src;
}

// ---------------- GEMM1 (tensor cores, tf32): z1 = x @ Wcat -----------------
// BM=128, BN=192, BK=16, 256 threads = 8 warps (4M x 2N), warp tile 32x96.
// Double-buffered smem + register staging: one syncthreads per K-iter.
__global__ void __launch_bounds__(256) gemm1_tc(const float* __restrict__ x,
                                                const float* __restrict__ W1) {
    __shared__ unsigned int As[2][128][20];
    __shared__ unsigned int Bs[2][16][196];
    const int m0 = blockIdx.x * 128;
    const int tid = threadIdx.x;
    const int wid = tid >> 5, lane = tid & 31;
    const int warp_m = wid >> 1;
    const int warp_n = wid & 1;
    const int lr = lane >> 2;
    const int lc = lane & 3;

    float acc[2][12][4];
    #pragma unroll
    for (int mt = 0; mt < 2; mt++)
        #pragma unroll
        for (int nt = 0; nt < 12; nt++)
            #pragma unroll
            for (int q = 0; q < 4; q++) acc[mt][nt][q] = 0.f;

    float4 ra[2], rb[3];

    #define LOAD_TILE(kk)                                                     \
        {                                                                     \
            _Pragma("unroll")                                                 \
            for (int r = 0; r < 2; r++) {                                     \
                int i = tid + r * 256;                                        \
                int row = i >> 2, q = i & 3;                                  \
                int gr = m0 + row;                                            \
                ra[r] = (gr < NN)                                             \
                    ? *(const float4*)(x + (size_t)gr * DIN + (kk) + q * 4)   \
                    : make_float4(0.f, 0.f, 0.f, 0.f);                        \
            }                                                                 \
            _Pragma("unroll")                                                 \
            for (int r = 0; r < 3; r++) {                                     \
                int i = tid + r * 256;                                        \
                int k = i / 48, cc = (i % 48) * 4;                            \
                int h = cc >> 6, j = cc & 63;                                 \
                rb[r] = *(const float4*)(W1 + h * (DIN * DHID)                \
                                          + (size_t)((kk) + k) * DHID + j);   \
            }                                                                 \
        }

    #define STORE_TILE(p)                                                     \
        {                                                                     \
            _Pragma("unroll")                                                 \
            for (int r = 0; r < 2; r++) {                                     \
                int i = tid + r * 256;                                        \
                int row = i >> 2, q = i & 3;                                  \
                As[p][row][q * 4 + 0] = f2tf32(ra[r].x);                      \
                As[p][row][q * 4 + 1] = f2tf32(ra[r].y);                      \
                As[p][row][q * 4 + 2] = f2tf32(ra[r].z);                      \
                As[p][row][q * 4 + 3] = f2tf32(ra[r].w);                      \
            }                                                                 \
            _Pragma("unroll")                                                 \
            for (int r = 0; r < 3; r++) {                                     \
                int i = tid + r * 256;                                        \
                int k = i / 48, cc = (i % 48) * 4;                            \
                Bs[p][k][cc + 0] = f2tf32(rb[r].x);                           \
                Bs[p][k][cc + 1] = f2tf32(rb[r].y);                           \
                Bs[p][k][cc + 2] = f2tf32(rb[r].z);                           \
                Bs[p][k][cc + 3] = f2tf32(rb[r].w);                           \
            }                                                                 \
        }

    LOAD_TILE(0);
    STORE_TILE(0);
    __syncthreads();

    int p = 0;
    for (int kk = 0; kk < DIN; kk += 16) {
        bool more = (kk + 16 < DIN);
        if (more) LOAD_TILE(kk + 16);
        #pragma unroll
        for (int ks = 0; ks < 2; ks++) {
            int kb = ks * 8;
            unsigned int afrag[2][4];
            #pragma unroll
            for (int mt = 0; mt < 2; mt++) {
                int m = warp_m * 32 + mt * 16 + lr;
                afrag[mt][0] = As[p][m][kb + lc];
                afrag[mt][1] = As[p][m + 8][kb + lc];
                afrag[mt][2] = As[p][m][kb + lc + 4];
                afrag[mt][3] = As[p][m + 8][kb + lc + 4];
            }
            #pragma unroll
            for (int nt = 0; nt < 12; nt++) {
                int n = warp_n * 96 + nt * 8 + lr;
                unsigned int bfrag[2];
                bfrag[0] = Bs[p][kb + lc][n];
                bfrag[1] = Bs[p][kb + lc + 4][n];
                mma_tf32(acc[0][nt], afrag[0], bfrag);
                mma_tf32(acc[1][nt], afrag[1], bfrag);
            }
        }
        if (more) {
            STORE_TILE(p ^ 1);
            __syncthreads();
            p ^= 1;
        }
    }
    #pragma unroll
    for (int mt = 0; mt < 2; mt++) {
        int row0 = m0 + warp_m * 32 + mt * 16 + lr;
        #pragma unroll
        for (int nt = 0; nt < 12; nt++) {
            int col = warp_n * 96 + nt * 8 + lc * 2;
            if (row0 < NN) {
                g_z1[(size_t)row0 * 192 + col]     = acc[mt][nt][0];
                g_z1[(size_t)row0 * 192 + col + 1] = acc[mt][nt][1];
            }
            if (row0 + 8 < NN) {
                g_z1[(size_t)(row0 + 8) * 192 + col]     = acc[mt][nt][2];
                g_z1[(size_t)(row0 + 8) * 192 + col + 1] = acc[mt][nt][3];
            }
        }
    }
    #undef LOAD_TILE
    #undef STORE_TILE
}

// ---------------- attention coefficients layer 1 (warp per (n,h)) ----------
__global__ void attn1_kernel(const float* __restrict__ as1,
                             const float* __restrict__ ad1) {
    int gw = (blockIdx.x * blockDim.x + threadIdx.x) >> 5;
    int lane = threadIdx.x & 31;
    if (gw >= NN * HH) return;
    int n = gw / HH, h = gw % HH;
    const float* z = g_z1 + (size_t)n * (HH * DHID) + h * DHID;
    const float* ws = as1 + h * DHID;
    const float* wd = ad1 + h * DHID;
    float vs = z[lane] * ws[lane] + z[lane + 32] * ws[lane + 32];
    float vd = z[lane] * wd[lane] + z[lane + 32] * wd[lane + 32];
    #pragma unroll
    for (int o = 16; o; o >>= 1) {
        vs += __shfl_xor_sync(0xffffffffu, vs, o);
        vd += __shfl_xor_sync(0xffffffffu, vd, o);
    }
    if (lane == 0) { g_es1[gw] = vs; g_ed1[gw] = vd; }
}

// ---------------- layer-1 fused gather-agg (96 threads, float2/thread) ------
// thread t covers cols 2t, 2t+1 (same head: h = t>>5). 4-edge unroll.
__global__ void __launch_bounds__(96) agg1_kernel() {
    int n = blockIdx.x;
    int t = threadIdx.x;            // 0..95
    int h = t >> 5;                 // 0..2
    __shared__ int s_src[64];
    __shared__ float s_ex[HH][64];
    __shared__ float s_red[192];
    int beg = g_ptr[n], end = g_ptr[n + 1];
    float2 acc0 = {0.f, 0.f}, acc1 = {0.f, 0.f};
    float2 acc2 = {0.f, 0.f}, acc3 = {0.f, 0.f};
    float den = 0.f;
    for (int base = beg; base < end; base += 64) {
        int cnt = min(64, end - base);
        __syncthreads();
        if (t < cnt) s_src[t] = g_csr_src[base + t];
        __syncthreads();
        #pragma unroll
        for (int i = t; i < HH * 64; i += 96) {
            int hh = i >> 6, j = i & 63;
            if (j < cnt) {
                float e = g_es1[s_src[j] * HH + hh] + g_ed1[n * HH + hh];
                e = (e > 0.f) ? e : 0.2f * e;
                s_ex[hh][j] = __expf(e);
            }
        }
        __syncthreads();
        const float* exb = s_ex[h];
        int p4 = cnt & ~3;
        for (int j = 0; j < p4; j += 4) {
            int s0 = s_src[j],     s1 = s_src[j + 1];
            int s2 = s_src[j + 2], s3 = s_src[j + 3];
            float2 z0 = *(const float2*)&g_z1[(size_t)s0 * 192 + 2 * t];
            float2 z1v = *(const float2*)&g_z1[(size_t)s1 * 192 + 2 * t];
            float2 z2v = *(const float2*)&g_z1[(size_t)s2 * 192 + 2 * t];
            float2 z3v = *(const float2*)&g_z1[(size_t)s3 * 192 + 2 * t];
            float ex0 = exb[j], ex1 = exb[j + 1];
            float ex2 = exb[j + 2], ex3 = exb[j + 3];
            den += (ex0 + ex1) + (ex2 + ex3);
            acc0.x += ex0 * z0.x;  acc0.y += ex0 * z0.y;
            acc1.x += ex1 * z1v.x; acc1.y += ex1 * z1v.y;
            acc2.x += ex2 * z2v.x; acc2.y += ex2 * z2v.y;
            acc3.x += ex3 * z3v.x; acc3.y += ex3 * z3v.y;
        }
        for (int j = p4; j < cnt; j++) {
            int s0 = s_src[j];
            float ex0 = exb[j];
            float2 z0 = *(const float2*)&g_z1[(size_t)s0 * 192 + 2 * t];
            den += ex0;
            acc0.x += ex0 * z0.x; acc0.y += ex0 * z0.y;
        }
    }
    float inv = 1.f / (den + 1e-16f);
    s_red[2 * t]     = (acc0.x + acc1.x + acc2.x + acc3.x) * inv;
    s_red[2 * t + 1] = (acc0.y + acc1.y + acc2.y + acc3.y) * inv;
    __syncthreads();
    if (t < 64) {
        float v = (s_red[t] + s_red[t + 64] + s_red[t + 128]) * (1.f / 3.f);
        g_h[n * DHID + t] = (v > 0.f) ? v : expm1f(v);
    }
}

// ---------------- GEMM2 (+fused attn2): z2, es2, ed2 ------------------------
__global__ void gemm2_kernel(const float* __restrict__ W2,
                             const float* __restrict__ as2,
                             const float* __restrict__ ad2) {
    __shared__ float hs[64][65];
    __shared__ float Ws[HH * DHID * DOUT];   // 1920
    __shared__ float z2s[64][30];
    int n0 = blockIdx.x * 64;
    int tid = threadIdx.x;
    for (int i = tid; i < HH * DHID * DOUT; i += 256) Ws[i] = W2[i];
    for (int i = tid; i < 64 * 64; i += 256) {
        int nl = i >> 6, d = i & 63;
        int gn = n0 + nl;
        hs[nl][d] = (gn < NN) ? g_h[(size_t)gn * DHID + d] : 0.f;
    }
    __syncthreads();
    for (int i = tid; i < 64 * HH * DOUT; i += 256) {
        int nl = i / 30, c = i - nl * 30;
        int gn = n0 + nl;
        int h = c / DOUT, o = c - h * DOUT;
        const float* w = Ws + h * (DHID * DOUT) + o;
        float s = 0.f;
        #pragma unroll
        for (int k = 0; k < DHID; k++) s += hs[nl][k] * w[k * DOUT];
        z2s[nl][c] = s;
        if (gn < NN) g_z2[(size_t)gn * (HH * DOUT) + c] = s;
    }
    __syncthreads();
    // fused attn2: 64 nodes x 3 heads = 192 (n,h) pairs
    for (int i = tid; i < 64 * HH; i += 256) {
        int nl = i / HH, h = i - nl * HH;
        int gn = n0 + nl;
        if (gn >= NN) continue;
        float vs = 0.f, vd = 0.f;
        #pragma unroll
        for (int o = 0; o < DOUT; o++) {
            float zv = z2s[nl][h * DOUT + o];
            vs += zv * __ldg(as2 + h * DOUT + o);
            vd += zv * __ldg(ad2 + h * DOUT + o);
        }
        g_es2[gn * HH + h] = vs;
        g_ed2[gn * HH + h] = vd;
    }
}

// ---------------- layer-2 fused gather-agg + mean + log_softmax -------------
// one warp per dst node; lanes 0..14 hold float2 col pairs (h = lane/5)
__global__ void agg2_kernel(float* __restrict__ out, int half) {
    int warp = (blockIdx.x * blockDim.x + threadIdx.x) >> 5;
    int lane = threadIdx.x & 31;
    if (warp >= NN) return;
    int n = warp;
    bool act = (lane < 15);
    int h = act ? (lane / 5) : 0;
    float ed = g_ed2[n * HH + h];
    int beg = g_ptr[n], end = g_ptr[n + 1];
    float2 acc0 = {0.f, 0.f}, acc1 = {0.f, 0.f};
    float2 acc2 = {0.f, 0.f}, acc3 = {0.f, 0.f};
    float den = 0.f;
    int p = beg;
    for (; p + 3 < end; p += 4) {
        int s0 = g_csr_src[p],     s1 = g_csr_src[p + 1];
        int s2 = g_csr_src[p + 2], s3 = g_csr_src[p + 3];
        float e0 = g_es2[s0 * HH + h] + ed;
        float e1 = g_es2[s1 * HH + h] + ed;
        float e2 = g_es2[s2 * HH + h] + ed;
        float e3 = g_es2[s3 * HH + h] + ed;
        e0 = (e0 > 0.f) ? e0 : 0.2f * e0;
        e1 = (e1 > 0.f) ? e1 : 0.2f * e1;
        e2 = (e2 > 0.f) ? e2 : 0.2f * e2;
        e3 = (e3 > 0.f) ? e3 : 0.2f * e3;
        float ex0 = __expf(e0), ex1 = __expf(e1);
        float ex2 = __expf(e2), ex3 = __expf(e3);
        den += (ex0 + ex1) + (ex2 + ex3);
        if (act) {
            float2 z0 = *(const float2*)&g_z2[(size_t)s0 * 30 + 2 * lane];
            float2 z1v = *(const float2*)&g_z2[(size_t)s1 * 30 + 2 * lane];
            float2 z2v = *(const float2*)&g_z2[(size_t)s2 * 30 + 2 * lane];
            float2 z3v = *(const float2*)&g_z2[(size_t)s3 * 30 + 2 * lane];
            acc0.x += ex0 * z0.x;  acc0.y += ex0 * z0.y;
            acc1.x += ex1 * z1v.x; acc1.y += ex1 * z1v.y;
            acc2.x += ex2 * z2v.x; acc2.y += ex2 * z2v.y;
            acc3.x += ex3 * z3v.x; acc3.y += ex3 * z3v.y;
        }
    }
    for (; p < end; p++) {
        int s0 = g_csr_src[p];
        float e0 = g_es2[s0 * HH + h] + ed;
        e0 = (e0 > 0.f) ? e0 : 0.2f * e0;
        float ex0 = __expf(e0);
        den += ex0;
        if (act) {
            float2 z0 = *(const float2*)&g_z2[(size_t)s0 * 30 + 2 * lane];
            acc0.x += ex0 * z0.x; acc0.y += ex0 * z0.y;
        }
    }
    float inv = 1.f / (den + 1e-16f);
    float2 s;
    s.x = (acc0.x + acc1.x + acc2.x + acc3.x) * inv;
    s.y = (acc0.y + acc1.y + acc2.y + acc3.y) * inv;
    // head combine: pair c needs pairs c+5, c+10
    float sx5  = __shfl_down_sync(0xffffffffu, s.x, 5);
    float sy5  = __shfl_down_sync(0xffffffffu, s.y, 5);
    float sx10 = __shfl_down_sync(0xffffffffu, s.x, 10);
    float sy10 = __shfl_down_sync(0xffffffffu, s.y, 10);
    float2 tpair;
    tpair.x = (s.x + sx5 + sx10) * (1.f / 3.f);
    tpair.y = (s.y + sy5 + sy10) * (1.f / 3.f);
    // log_softmax over 10 values held as 5 lane-pairs (lanes 0..4)
    bool out5 = (lane < 5);
    float mloc = out5 ? fmaxf(tpair.x, tpair.y) : -INFINITY;
    #pragma unroll
    for (int o = 4; o; o >>= 1)
        mloc = fmaxf(mloc, __shfl_xor_sync(0xffffffffu, mloc, o, 8));
    float eloc = out5 ? (__expf(tpair.x - mloc) + __expf(tpair.y - mloc)) : 0.f;
    #pragma unroll
    for (int o = 4; o; o >>= 1)
        eloc += __shfl_xor_sync(0xffffffffu, eloc, o, 8);
    float lse = __logf(eloc) + mloc;
    if (out5) {
        out[(size_t)n * DOUT + 2 * lane]     = tpair.x;
        out[(size_t)n * DOUT + 2 * lane + 1] = tpair.y;
        out[half + (size_t)n * DOUT + 2 * lane]     = tpair.x - lse;
        out[half + (size_t)n * DOUT + 2 * lane + 1] = tpair.y - lse;
    }
}

// ---------------- launcher --------------------------------------------------
extern "C" void kernel_launch(void* const* d_in, const int* in_sizes, int n_in,
                              void* d_out, int out_size) {
    const float* x   = (const float*)d_in[0];
    const int*   ei  = (const int*)d_in[1];
    const float* W1  = (const float*)d_in[2];
    const float* as1 = (const float*)d_in[3];
    const float* ad1 = (const float*)d_in[4];
    const float* W2  = (const float*)d_in[5];
    const float* as2 = (const float*)d_in[6];
    const float* ad2 = (const float*)d_in[7];
    float* out = (float*)d_out;
    int half = out_size / 2;

    if (g_sh.ok) {
        cudaEventRecord(g_sh.e1, 0);
        cudaStreamWaitEvent(g_sh.s2, g_sh.e1, 0);
        csr_zero<<<(NN + 255) / 256, 256, 0, g_sh.s2>>>();
        csr_hist<<<(EE + 255) / 256, 256, 0, g_sh.s2>>>(ei);
        csr_scan<<<1, 1024, 0, g_sh.s2>>>();
        csr_scatter<<<(EE + 255) / 256, 256, 0, g_sh.s2>>>(ei);
        cudaEventRecord(g_sh.e2, g_sh.s2);

        gemm1_tc<<<(NN + 127) / 128, 256>>>(x, W1);
        attn1_kernel<<<(NN * HH * 32 + 255) / 256, 256>>>(as1, ad1);

        cudaStreamWaitEvent(0, g_sh.e2, 0);
    } else {
        csr_zero<<<(NN + 255) / 256, 256>>>();
        csr_hist<<<(EE + 255) / 256, 256>>>(ei);
        csr_scan<<<1, 1024>>>();
        csr_scatter<<<(EE + 255) / 256, 256>>>(ei);
        gemm1_tc<<<(NN + 127) / 128, 256>>>(x, W1);
        attn1_kernel<<<(NN * HH * 32 + 255) / 256, 256>>>(as1, ad1);
    }

    agg1_kernel<<<NN, 96>>>();

    gemm2_kernel<<<(NN + 63) / 64, 256>>>(W2, as2, ad2);
    agg2_kernel<<<(NN * 32 + 255) / 256, 256>>>(out, half);
}